// round 7
// baseline (speedup 1.0000x reference)
#include <cuda_runtime.h>
#include <cstdint>

#define MAXV 50000
#define MAXE 800000
#define NODE_IN 128
#define EDGE_IN 16
#define HF 128
#define HEADS 4
#define OUTF 32
#define NEG_SLOPE 0.2f
#define ETILE 64
#define PROJ_ROWS 128
#define XS_LD 132   // padded smem stride (floats) -> conflict-free A frags

// ---------------- device scratch ----------------
__device__ float g_ft[MAXV * HF];
__device__ float g_el[MAXV * HEADS];
__device__ float g_er[MAXV * HEADS];
__device__ float g_esum[MAXV * HEADS];
__device__ float g_ex[MAXE * HEADS];    // holds ee first, then exp() in-place
__device__ int   g_deg[MAXV];
__device__ int   g_incl[MAXV];
__device__ int   g_bsum[64];
__device__ int   g_rowptr[MAXV + 1];
__device__ int   g_cursor[MAXV];
__device__ int   g_csr[MAXE];
__device__ float g_wer[EDGE_IN * HEADS];
__device__ unsigned g_wnr[NODE_IN * HF];
__device__ unsigned g_wrr[NODE_IN * HF];

__device__ __forceinline__ unsigned tf32r(float x) {
    unsigned u;
    asm("cvt.rna.tf32.f32 %0, %1;" : "=r"(u) : "f"(x));
    return u;
}

__device__ __forceinline__ void mma_tf32(float* d, const unsigned* a, const unsigned* b) {
    asm volatile(
        "mma.sync.aligned.m16n8k8.row.col.f32.tf32.tf32.f32 "
        "{%0,%1,%2,%3}, {%4,%5,%6,%7}, {%8,%9}, {%0,%1,%2,%3};"
        : "+f"(d[0]), "+f"(d[1]), "+f"(d[2]), "+f"(d[3])
        : "r"(a[0]), "r"(a[1]), "r"(a[2]), "r"(a[3]), "r"(b[0]), "r"(b[1]));
}

// ---------------- CSR-build kernels (side stream) ----------------
__global__ void k_zero(int V) {
    int i = blockIdx.x * blockDim.x + threadIdx.x;
    if (i < V) g_deg[i] = 0;
    if (i < V * HEADS) g_esum[i] = 0.0f;
}

__global__ void k_hist(const int* __restrict__ dst, int E) {
    int i = blockIdx.x * blockDim.x + threadIdx.x;
    if (i < E) atomicAdd(&g_deg[dst[i]], 1);
}

__global__ void k_scan1(int V) {
    __shared__ int wsum[32];
    int b = blockIdx.x, t = threadIdx.x;
    int i = b * 1024 + t;
    int val = (i < V) ? g_deg[i] : 0;
    int lane = t & 31, wid = t >> 5;
    int x = val;
    #pragma unroll
    for (int o = 1; o < 32; o <<= 1) {
        int y = __shfl_up_sync(0xFFFFFFFFu, x, o);
        if (lane >= o) x += y;
    }
    if (lane == 31) wsum[wid] = x;
    __syncthreads();
    if (wid == 0) {
        int s = wsum[lane];
        #pragma unroll
        for (int o = 1; o < 32; o <<= 1) {
            int y = __shfl_up_sync(0xFFFFFFFFu, s, o);
            if (lane >= o) s += y;
        }
        wsum[lane] = s;
    }
    __syncthreads();
    int incl = x + (wid > 0 ? wsum[wid - 1] : 0);
    if (i < V) g_incl[i] = incl;
    if (t == 1023) g_bsum[b] = incl;
}

__global__ void k_scan3(int V) {
    __shared__ int soff;
    int b = blockIdx.x, t = threadIdx.x;
    if (t < 32) {
        int s = 0;
        for (int j = t; j < b; j += 32) s += g_bsum[j];
        #pragma unroll
        for (int o = 16; o > 0; o >>= 1) s += __shfl_xor_sync(0xFFFFFFFFu, s, o);
        if (t == 0) soff = s;
    }
    __syncthreads();
    int i = b * 1024 + t;
    if (i < V) {
        int incl = g_incl[i] + soff;
        g_rowptr[i + 1] = incl;
        g_cursor[i] = incl - g_deg[i];
        if (i == 0) g_rowptr[0] = 0;
    }
}

__global__ void k_fill(const int* __restrict__ dst, int E) {
    int i = blockIdx.x * blockDim.x + threadIdx.x;
    if (i < E) {
        int pos = atomicAdd(&g_cursor[dst[i]], 1);
        g_csr[pos] = i;
    }
}

// edge-feature logits ee = ef @ wer  (independent of node projection;
// runs on the side stream overlapped with k_nodeproj). Stores into g_ex.
__global__ void k_ee(const float* __restrict__ ef, int E) {
    __shared__ float swer[EDGE_IN * HEADS];
    if (threadIdx.x < EDGE_IN * HEADS) swer[threadIdx.x] = g_wer[threadIdx.x];
    __syncthreads();

    int i = blockIdx.x * blockDim.x + threadIdx.x;
    if (i >= E) return;

    float efv[16];
    #pragma unroll
    for (int q = 0; q < 4; q++) {
        float4 e4 = __ldg(reinterpret_cast<const float4*>(ef + (size_t)i * EDGE_IN + q * 4));
        efv[q * 4 + 0] = e4.x; efv[q * 4 + 1] = e4.y; efv[q * 4 + 2] = e4.z; efv[q * 4 + 3] = e4.w;
    }
    float ee0 = 0.f, ee1 = 0.f, ee2 = 0.f, ee3 = 0.f;
    #pragma unroll
    for (int j = 0; j < EDGE_IN; j++) {
        float e = efv[j];
        ee0 += e * swer[j * 4 + 0];
        ee1 += e * swer[j * 4 + 1];
        ee2 += e * swer[j * 4 + 2];
        ee3 += e * swer[j * 4 + 3];
    }
    *reinterpret_cast<float4*>(&g_ex[(size_t)i * HEADS]) = make_float4(ee0, ee1, ee2, ee3);
}

// ---------------- fold + tf32 weight rounding ----------------
__global__ void k_fold(const float* __restrict__ We, const float* __restrict__ ae,
                       const float* __restrict__ Wn, const float* __restrict__ Wr) {
    int i = blockIdx.x * blockDim.x + threadIdx.x;
    if (i < NODE_IN * HF) {
        g_wnr[i] = tf32r(Wn[i]);
        g_wrr[i] = tf32r(Wr[i]);
    }
    if (blockIdx.x == 0 && threadIdx.x < EDGE_IN * HEADS) {
        int t = threadIdx.x;
        int j = t >> 2, h = t & 3;
        float s = 0.0f;
        #pragma unroll
        for (int f = 0; f < OUTF; f++)
            s += We[j * HF + h * OUTF + f] * ae[h * OUTF + f];
        g_wer[j * HEADS + h] = s;
    }
}

// ---------------- node projection via TF32 HMMA ----------------
// 512 threads, 128-row tile. Warp grid 2 (row halves of 64) x 8 (col groups).
// Warp tile: 4 m16 tiles x 4 n8 tiles, k=128 in 16 steps.
// Per k-step: 8 B-LDGs amortized over 16 MMAs (2x better than round 6).
__global__ void __launch_bounds__(512) k_nodeproj(
    const float* __restrict__ nf, const float* __restrict__ bias,
    const float* __restrict__ al, const float* __restrict__ ar,
    float* __restrict__ out, int V)
{
    extern __shared__ float xs[];   // [128][XS_LD]
    int v0 = blockIdx.x * PROJ_ROWS;
    int tid = threadIdx.x;

    #pragma unroll
    for (int i = 0; i < 8; i++) {
        int idx = tid + i * 512;          // 0..4095 float4 slots
        int r = idx >> 5;                 // row 0..127
        int c4 = idx & 31;
        int v = v0 + r;
        float4 val = make_float4(0.f, 0.f, 0.f, 0.f);
        if (v < V) val = *reinterpret_cast<const float4*>(nf + (size_t)v * NODE_IN + c4 * 4);
        val.x = __uint_as_float(tf32r(val.x));
        val.y = __uint_as_float(tf32r(val.y));
        val.z = __uint_as_float(tf32r(val.z));
        val.w = __uint_as_float(tf32r(val.w));
        *reinterpret_cast<float4*>(&xs[r * XS_LD + c4 * 4]) = val;
    }
    __syncthreads();

    int lane = tid & 31;
    int warp = tid >> 5;
    int wrow = warp & 1;                  // row half: 64 rows
    int wcg  = warp >> 1;                 // col group 0..7
    int tig  = lane & 3;
    int gid  = lane >> 2;

    const unsigned* B = (wcg < 4) ? g_wnr : g_wrr;
    int nb = (wcg & 3) * 32;
    int mbase = wrow * 64;

    float acc[4][4][4];
    #pragma unroll
    for (int mt = 0; mt < 4; mt++)
        #pragma unroll
        for (int nt = 0; nt < 4; nt++)
            #pragma unroll
            for (int q = 0; q < 4; q++) acc[mt][nt][q] = 0.f;

    #pragma unroll 2
    for (int ks = 0; ks < 16; ks++) {
        int kb = ks * 8;
        unsigned b[4][2];
        #pragma unroll
        for (int nt = 0; nt < 4; nt++) {
            int col = nb + nt * 8 + gid;
            b[nt][0] = __ldg(&B[(kb + tig) * HF + col]);
            b[nt][1] = __ldg(&B[(kb + tig + 4) * HF + col]);
        }
        #pragma unroll
        for (int mt = 0; mt < 4; mt++) {
            unsigned a[4];
            int r0 = mbase + mt * 16 + gid;
            a[0] = __float_as_uint(xs[r0 * XS_LD + kb + tig]);
            a[1] = __float_as_uint(xs[(r0 + 8) * XS_LD + kb + tig]);
            a[2] = __float_as_uint(xs[r0 * XS_LD + kb + tig + 4]);
            a[3] = __float_as_uint(xs[(r0 + 8) * XS_LD + kb + tig + 4]);
            #pragma unroll
            for (int nt = 0; nt < 4; nt++)
                mma_tf32(acc[mt][nt], a, b[nt]);
        }
    }

    if (wcg < 4) {
        int h = wcg;
        float2 alf[4], arf[4];
        #pragma unroll
        for (int nt = 0; nt < 4; nt++) {
            alf[nt] = *reinterpret_cast<const float2*>(al + h * OUTF + nt * 8 + 2 * tig);
            arf[nt] = *reinterpret_cast<const float2*>(ar + h * OUTF + nt * 8 + 2 * tig);
        }
        #pragma unroll
        for (int mt = 0; mt < 4; mt++) {
            int r0 = v0 + mbase + mt * 16 + gid;
            float el0 = 0.f, el1 = 0.f, er0 = 0.f, er1 = 0.f;
            #pragma unroll
            for (int nt = 0; nt < 4; nt++) {
                el0 += acc[mt][nt][0] * alf[nt].x + acc[mt][nt][1] * alf[nt].y;
                el1 += acc[mt][nt][2] * alf[nt].x + acc[mt][nt][3] * alf[nt].y;
                er0 += acc[mt][nt][0] * arf[nt].x + acc[mt][nt][1] * arf[nt].y;
                er1 += acc[mt][nt][2] * arf[nt].x + acc[mt][nt][3] * arf[nt].y;
                if (r0 < V)
                    *reinterpret_cast<float2*>(g_ft + (size_t)r0 * HF + h * OUTF + nt * 8 + 2 * tig)
                        = make_float2(acc[mt][nt][0], acc[mt][nt][1]);
                if (r0 + 8 < V)
                    *reinterpret_cast<float2*>(g_ft + (size_t)(r0 + 8) * HF + h * OUTF + nt * 8 + 2 * tig)
                        = make_float2(acc[mt][nt][2], acc[mt][nt][3]);
            }
            el0 += __shfl_xor_sync(0xFFFFFFFFu, el0, 1); el0 += __shfl_xor_sync(0xFFFFFFFFu, el0, 2);
            el1 += __shfl_xor_sync(0xFFFFFFFFu, el1, 1); el1 += __shfl_xor_sync(0xFFFFFFFFu, el1, 2);
            er0 += __shfl_xor_sync(0xFFFFFFFFu, er0, 1); er0 += __shfl_xor_sync(0xFFFFFFFFu, er0, 2);
            er1 += __shfl_xor_sync(0xFFFFFFFFu, er1, 1); er1 += __shfl_xor_sync(0xFFFFFFFFu, er1, 2);
            if (tig == 0) {
                if (r0 < V)     { g_el[r0 * HEADS + h] = el0;       g_er[r0 * HEADS + h] = er0; }
                if (r0 + 8 < V) { g_el[(r0 + 8) * HEADS + h] = el1; g_er[(r0 + 8) * HEADS + h] = er1; }
            }
        }
    } else {
        int cb = (wcg - 4) * 32;
        float2 bv[4];
        #pragma unroll
        for (int nt = 0; nt < 4; nt++)
            bv[nt] = *reinterpret_cast<const float2*>(bias + cb + nt * 8 + 2 * tig);
        #pragma unroll
        for (int mt = 0; mt < 4; mt++) {
            int r0 = v0 + mbase + mt * 16 + gid;
            #pragma unroll
            for (int nt = 0; nt < 4; nt++) {
                int col = cb + nt * 8 + 2 * tig;
                if (r0 < V)
                    *reinterpret_cast<float2*>(out + (size_t)r0 * HF + col)
                        = make_float2(acc[mt][nt][0] + bv[nt].x, acc[mt][nt][1] + bv[nt].y);
                if (r0 + 8 < V)
                    *reinterpret_cast<float2*>(out + (size_t)(r0 + 8) * HF + col)
                        = make_float2(acc[mt][nt][2] + bv[nt].x, acc[mt][nt][3] + bv[nt].y);
            }
        }
    }
}

// ---------------- edge logits part 2: el/er gather + exp + denominator ---
__global__ void k_edge2(const int* __restrict__ src, const int* __restrict__ dst, int E)
{
    int i = blockIdx.x * blockDim.x + threadIdx.x;
    if (i >= E) return;

    float4 ee4 = *reinterpret_cast<const float4*>(&g_ex[(size_t)i * HEADS]);
    int s = src[i], d = dst[i];
    float4 el4 = *reinterpret_cast<const float4*>(&g_el[s * HEADS]);
    float4 er4 = *reinterpret_cast<const float4*>(&g_er[d * HEADS]);

    float t0 = el4.x + er4.x + ee4.x;
    float t1 = el4.y + er4.y + ee4.y;
    float t2 = el4.z + er4.z + ee4.z;
    float t3 = el4.w + er4.w + ee4.w;
    t0 = (t0 >= 0.f) ? t0 : NEG_SLOPE * t0;
    t1 = (t1 >= 0.f) ? t1 : NEG_SLOPE * t1;
    t2 = (t2 >= 0.f) ? t2 : NEG_SLOPE * t2;
    t3 = (t3 >= 0.f) ? t3 : NEG_SLOPE * t3;
    // softmax is shift-invariant; logits are O(1) -> no max pass
    float x0 = __expf(t0), x1 = __expf(t1), x2 = __expf(t2), x3 = __expf(t3);

    *reinterpret_cast<float4*>(&g_ex[(size_t)i * HEADS]) = make_float4(x0, x1, x2, x3);

    float* ep = &g_esum[d * HEADS];
    asm volatile("red.global.add.v4.f32 [%0], {%1,%2,%3,%4};"
                 :: "l"(ep), "f"(x0), "f"(x1), "f"(x2), "f"(x3) : "memory");
}

// ---------------- aggregation: one block per dst ----------------
__global__ void __launch_bounds__(128) k_agg(const int* __restrict__ src,
                                             float* __restrict__ out, int V)
{
    __shared__ int   s_src[ETILE];
    __shared__ float s_a[HEADS][ETILE];
    __shared__ float4 s_red[3][32];

    int v = blockIdx.x;
    int t = threadIdx.x, w = t >> 5, lane = t & 31;
    int beg = g_rowptr[v], end = g_rowptr[v + 1];
    if (end <= beg) return;

    float4 es = *reinterpret_cast<const float4*>(&g_esum[v * HEADS]);
    float iv0 = 1.0f / es.x, iv1 = 1.0f / es.y, iv2 = 1.0f / es.z, iv3 = 1.0f / es.w;

    int h = lane >> 3;
    float4 acc = make_float4(0.f, 0.f, 0.f, 0.f);

    for (int pos = beg; pos < end; pos += ETILE) {
        int cnt = min(ETILE, end - pos);
        __syncthreads();
        if (t < cnt) {
            int eid = g_csr[pos + t];
            s_src[t] = src[eid];
            float4 ex = *reinterpret_cast<const float4*>(&g_ex[(size_t)eid * HEADS]);
            s_a[0][t] = ex.x * iv0;
            s_a[1][t] = ex.y * iv1;
            s_a[2][t] = ex.z * iv2;
            s_a[3][t] = ex.w * iv3;
        }
        __syncthreads();
        #pragma unroll 2
        for (int j = w; j < cnt; j += 4) {
            int sv = s_src[j];
            float a = s_a[h][j];
            float4 f = __ldg(reinterpret_cast<const float4*>(g_ft + (size_t)sv * HF + lane * 4));
            acc.x += a * f.x; acc.y += a * f.y; acc.z += a * f.z; acc.w += a * f.w;
        }
    }

    if (w > 0) s_red[w - 1][lane] = acc;
    __syncthreads();
    if (w == 0) {
        acc.x += s_red[0][lane].x + s_red[1][lane].x + s_red[2][lane].x;
        acc.y += s_red[0][lane].y + s_red[1][lane].y + s_red[2][lane].y;
        acc.z += s_red[0][lane].z + s_red[1][lane].z + s_red[2][lane].z;
        acc.w += s_red[0][lane].w + s_red[1][lane].w + s_red[2][lane].w;
        float4* op = reinterpret_cast<float4*>(out + (size_t)v * HF + lane * 4);
        float4 o = *op;
        o.x += acc.x; o.y += acc.y; o.z += acc.z; o.w += acc.w;
        *op = o;
    }
}

// ---------------- launch with forked capture streams ----------------
static cudaStream_t g_s2 = nullptr;
static cudaEvent_t g_evFork = nullptr, g_evJoin = nullptr, g_evEE = nullptr, g_evFold = nullptr;
static bool g_attr = false;

extern "C" void kernel_launch(void* const* d_in, const int* in_sizes, int n_in,
                              void* d_out, int out_size)
{
    const float* nf   = (const float*)d_in[0];
    const float* ef   = (const float*)d_in[1];
    const int*   src  = (const int*)d_in[2];
    const int*   dst  = (const int*)d_in[3];
    const float* Wn   = (const float*)d_in[4];
    const float* We   = (const float*)d_in[5];
    const float* al   = (const float*)d_in[6];
    const float* ar   = (const float*)d_in[7];
    const float* ae   = (const float*)d_in[8];
    const float* Wr   = (const float*)d_in[9];
    const float* bias = (const float*)d_in[10];
    float* out = (float*)d_out;

    int V = in_sizes[0] / NODE_IN;
    int E = in_sizes[2];
    if (V > MAXV) V = MAXV;
    if (E > MAXE) E = MAXE;

    if (!g_s2) {
        cudaStreamCreateWithFlags(&g_s2, cudaStreamNonBlocking);
        cudaEventCreateWithFlags(&g_evFork, cudaEventDisableTiming);
        cudaEventCreateWithFlags(&g_evJoin, cudaEventDisableTiming);
        cudaEventCreateWithFlags(&g_evEE, cudaEventDisableTiming);
        cudaEventCreateWithFlags(&g_evFold, cudaEventDisableTiming);
    }
    const int smemProj = PROJ_ROWS * XS_LD * sizeof(float);   // ~67.6 KB
    if (!g_attr) {
        cudaFuncSetAttribute(k_nodeproj, cudaFuncAttributeMaxDynamicSharedMemorySize, smemProj);
        g_attr = true;
    }

    int nch = (V + 1023) / 1024;

    cudaEventRecord(g_evFork, 0);
    cudaStreamWaitEvent(g_s2, g_evFork, 0);

    k_fold<<<(NODE_IN * HF + 255) / 256, 256>>>(We, ae, Wn, Wr);   // #1 main
    cudaEventRecord(g_evFold, 0);
    k_zero<<<(V * HEADS + 255) / 256, 256, 0, g_s2>>>(V);          // #2 side
    k_hist<<<(E + 255) / 256, 256, 0, g_s2>>>(dst, E);             // #3 side
    k_nodeproj<<<(V + PROJ_ROWS - 1) / PROJ_ROWS, 512, smemProj>>>(nf, bias, al, ar, out, V);  // #4 main (profiled)
    cudaStreamWaitEvent(g_s2, g_evFold, 0);
    k_ee<<<(E + 127) / 128, 128, 0, g_s2>>>(ef, E);                // #5 side (overlaps nodeproj)
    cudaEventRecord(g_evEE, g_s2);
    k_scan1<<<nch, 1024, 0, g_s2>>>(V);                            // #6 side
    k_scan3<<<nch, 1024, 0, g_s2>>>(V);                            // #7 side
    k_fill<<<(E + 255) / 256, 256, 0, g_s2>>>(dst, E);             // #8 side
    cudaEventRecord(g_evJoin, g_s2);

    cudaStreamWaitEvent(0, g_evEE, 0);
    k_edge2<<<(E + 255) / 256, 256>>>(src, dst, E);                // #9 main

    cudaStreamWaitEvent(0, g_evJoin, 0);
    k_agg<<<V, 128>>>(src, out, V);                                // #10 main
}

// round 8
// speedup vs baseline: 1.5068x; 1.5068x over previous
#include <cuda_runtime.h>
#include <cuda_fp16.h>
#include <cstdint>

#define MAXV 50000
#define MAXE 800000
#define NODE_IN 128
#define EDGE_IN 16
#define HF 128
#define HEADS 4
#define OUTF 32
#define NEG_SLOPE 0.2f
#define ETILE 64
#define PROJ_ROWS 64
#define XS_LD 132   // padded smem stride (floats) -> conflict-free A frags

// ---------------- device scratch ----------------
__device__ __half g_fth[MAXV * HF];     // projected node feats (fp16)
__device__ float g_el[MAXV * HEADS];
__device__ float g_er[MAXV * HEADS];
__device__ float g_esum[MAXV * HEADS];
__device__ float g_ex[MAXE * HEADS];
__device__ int   g_deg[MAXV];
__device__ int   g_incl[MAXV];
__device__ int   g_bsum[64];
__device__ int   g_rowptr[MAXV + 1];
__device__ int   g_cursor[MAXV];
__device__ int   g_csr[MAXE];
__device__ float g_wer[EDGE_IN * HEADS];
// pair-packed tf32 weights: index ((ks*HF + col)*4 + tig) -> (k=ks*8+tig, k+4)
__device__ uint2 g_wnr2[(NODE_IN / 8) * HF * 4];
__device__ uint2 g_wrr2[(NODE_IN / 8) * HF * 4];

__device__ __forceinline__ unsigned tf32r(float x) {
    unsigned u;
    asm("cvt.rna.tf32.f32 %0, %1;" : "=r"(u) : "f"(x));
    return u;
}

__device__ __forceinline__ void mma_tf32(float* d, const unsigned* a, const unsigned* b) {
    asm volatile(
        "mma.sync.aligned.m16n8k8.row.col.f32.tf32.tf32.f32 "
        "{%0,%1,%2,%3}, {%4,%5,%6,%7}, {%8,%9}, {%0,%1,%2,%3};"
        : "+f"(d[0]), "+f"(d[1]), "+f"(d[2]), "+f"(d[3])
        : "r"(a[0]), "r"(a[1]), "r"(a[2]), "r"(a[3]), "r"(b[0]), "r"(b[1]));
}

// ---------------- CSR-build kernels (side stream) ----------------
__global__ void k_zero(int V) {
    int i = blockIdx.x * blockDim.x + threadIdx.x;
    if (i < V) g_deg[i] = 0;
    if (i < V * HEADS) g_esum[i] = 0.0f;
}

__global__ void k_hist(const int* __restrict__ dst, int E) {
    int i = blockIdx.x * blockDim.x + threadIdx.x;
    if (i < E) atomicAdd(&g_deg[dst[i]], 1);
}

__global__ void k_scan1(int V) {
    __shared__ int wsum[32];
    int b = blockIdx.x, t = threadIdx.x;
    int i = b * 1024 + t;
    int val = (i < V) ? g_deg[i] : 0;
    int lane = t & 31, wid = t >> 5;
    int x = val;
    #pragma unroll
    for (int o = 1; o < 32; o <<= 1) {
        int y = __shfl_up_sync(0xFFFFFFFFu, x, o);
        if (lane >= o) x += y;
    }
    if (lane == 31) wsum[wid] = x;
    __syncthreads();
    if (wid == 0) {
        int s = wsum[lane];
        #pragma unroll
        for (int o = 1; o < 32; o <<= 1) {
            int y = __shfl_up_sync(0xFFFFFFFFu, s, o);
            if (lane >= o) s += y;
        }
        wsum[lane] = s;
    }
    __syncthreads();
    int incl = x + (wid > 0 ? wsum[wid - 1] : 0);
    if (i < V) g_incl[i] = incl;
    if (t == 1023) g_bsum[b] = incl;
}

__global__ void k_scan3(int V) {
    __shared__ int soff;
    int b = blockIdx.x, t = threadIdx.x;
    if (t < 32) {
        int s = 0;
        for (int j = t; j < b; j += 32) s += g_bsum[j];
        #pragma unroll
        for (int o = 16; o > 0; o >>= 1) s += __shfl_xor_sync(0xFFFFFFFFu, s, o);
        if (t == 0) soff = s;
    }
    __syncthreads();
    int i = b * 1024 + t;
    if (i < V) {
        int incl = g_incl[i] + soff;
        g_rowptr[i + 1] = incl;
        g_cursor[i] = incl - g_deg[i];
        if (i == 0) g_rowptr[0] = 0;
    }
}

__global__ void k_fill(const int* __restrict__ dst, int E) {
    int i = blockIdx.x * blockDim.x + threadIdx.x;
    if (i < E) {
        int pos = atomicAdd(&g_cursor[dst[i]], 1);
        g_csr[pos] = i;
    }
}

// ---------------- fold + tf32 weight rounding into pair-packed layout ----
__global__ void k_fold(const float* __restrict__ We, const float* __restrict__ ae,
                       const float* __restrict__ Wn, const float* __restrict__ Wr) {
    int i = blockIdx.x * blockDim.x + threadIdx.x;
    int NP = (NODE_IN / 8) * HF * 4;     // 8192
    if (i < NP) {
        int ks  = i >> 9;                // /(HF*4)
        int col = (i >> 2) & (HF - 1);
        int tig = i & 3;
        int k0 = ks * 8 + tig;
        g_wnr2[i] = make_uint2(tf32r(Wn[(size_t)k0 * HF + col]),
                               tf32r(Wn[(size_t)(k0 + 4) * HF + col]));
        g_wrr2[i] = make_uint2(tf32r(Wr[(size_t)k0 * HF + col]),
                               tf32r(Wr[(size_t)(k0 + 4) * HF + col]));
    }
    if (blockIdx.x == 0 && threadIdx.x < EDGE_IN * HEADS) {
        int t = threadIdx.x;
        int j = t >> 2, h = t & 3;
        float s = 0.0f;
        #pragma unroll
        for (int f = 0; f < OUTF; f++)
            s += We[j * HF + h * OUTF + f] * ae[h * OUTF + f];
        g_wer[j * HEADS + h] = s;
    }
}

// ---------------- node projection via TF32 HMMA ----------------
// 512 threads, 64-row tile. Warp grid 2 (rows) x 8 (col groups of 32).
// Warp tile: 2 m16 x 4 n8, k=128 in 16 steps. B via pair-packed LDG.64
// (warp-contiguous 256B per nt). ft stored fp16.
__global__ void __launch_bounds__(512) k_nodeproj(
    const float* __restrict__ nf, const float* __restrict__ bias,
    const float* __restrict__ al, const float* __restrict__ ar,
    float* __restrict__ out, int V)
{
    extern __shared__ float xs[];   // [64][XS_LD]
    int v0 = blockIdx.x * PROJ_ROWS;
    int tid = threadIdx.x;

    #pragma unroll
    for (int i = 0; i < 4; i++) {
        int idx = tid + i * 512;          // 0..2047 float4 slots
        int r = idx >> 5;                 // row 0..63
        int c4 = idx & 31;
        int v = v0 + r;
        float4 val = make_float4(0.f, 0.f, 0.f, 0.f);
        if (v < V) val = *reinterpret_cast<const float4*>(nf + (size_t)v * NODE_IN + c4 * 4);
        val.x = __uint_as_float(tf32r(val.x));
        val.y = __uint_as_float(tf32r(val.y));
        val.z = __uint_as_float(tf32r(val.z));
        val.w = __uint_as_float(tf32r(val.w));
        *reinterpret_cast<float4*>(&xs[r * XS_LD + c4 * 4]) = val;
    }
    __syncthreads();

    int lane = tid & 31;
    int warp = tid >> 5;                  // 0..15
    int wrow = warp & 1;
    int wcg  = warp >> 1;                 // col group 0..7
    int tig  = lane & 3;
    int gid  = lane >> 2;

    const uint2* B2 = (wcg < 4) ? g_wnr2 : g_wrr2;
    int nb = (wcg & 3) * 32;
    int mbase = wrow * 32;

    float acc[2][4][4];
    #pragma unroll
    for (int mt = 0; mt < 2; mt++)
        #pragma unroll
        for (int nt = 0; nt < 4; nt++)
            #pragma unroll
            for (int q = 0; q < 4; q++) acc[mt][nt][q] = 0.f;

    #pragma unroll 4
    for (int ks = 0; ks < 16; ks++) {
        int kb = ks * 8;
        unsigned a[2][4];
        #pragma unroll
        for (int mt = 0; mt < 2; mt++) {
            int r0 = mbase + mt * 16 + gid;
            a[mt][0] = __float_as_uint(xs[r0 * XS_LD + kb + tig]);
            a[mt][1] = __float_as_uint(xs[(r0 + 8) * XS_LD + kb + tig]);
            a[mt][2] = __float_as_uint(xs[r0 * XS_LD + kb + tig + 4]);
            a[mt][3] = __float_as_uint(xs[(r0 + 8) * XS_LD + kb + tig + 4]);
        }
        unsigned b[4][2];
        #pragma unroll
        for (int nt = 0; nt < 4; nt++) {
            int col = nb + nt * 8 + gid;
            uint2 bp = __ldg(&B2[(ks * HF + col) * 4 + tig]);
            b[nt][0] = bp.x;
            b[nt][1] = bp.y;
        }
        #pragma unroll
        for (int mt = 0; mt < 2; mt++)
            #pragma unroll
            for (int nt = 0; nt < 4; nt++)
                mma_tf32(acc[mt][nt], a[mt], b[nt]);
    }

    if (wcg < 4) {
        // ft (fp16) store + fused el/er; head h = wcg
        int h = wcg;
        float2 alf[4], arf[4];
        #pragma unroll
        for (int nt = 0; nt < 4; nt++) {
            alf[nt] = *reinterpret_cast<const float2*>(al + h * OUTF + nt * 8 + 2 * tig);
            arf[nt] = *reinterpret_cast<const float2*>(ar + h * OUTF + nt * 8 + 2 * tig);
        }
        #pragma unroll
        for (int mt = 0; mt < 2; mt++) {
            int r0 = v0 + mbase + mt * 16 + gid;
            float el0 = 0.f, el1 = 0.f, er0 = 0.f, er1 = 0.f;
            #pragma unroll
            for (int nt = 0; nt < 4; nt++) {
                el0 += acc[mt][nt][0] * alf[nt].x + acc[mt][nt][1] * alf[nt].y;
                el1 += acc[mt][nt][2] * alf[nt].x + acc[mt][nt][3] * alf[nt].y;
                er0 += acc[mt][nt][0] * arf[nt].x + acc[mt][nt][1] * arf[nt].y;
                er1 += acc[mt][nt][2] * arf[nt].x + acc[mt][nt][3] * arf[nt].y;
                int ci = h * 16 + nt * 4 + tig;   // half2 col index
                if (r0 < V)
                    *reinterpret_cast<__half2*>(g_fth + (size_t)r0 * HF + 2 * ci)
                        = __floats2half2_rn(acc[mt][nt][0], acc[mt][nt][1]);
                if (r0 + 8 < V)
                    *reinterpret_cast<__half2*>(g_fth + (size_t)(r0 + 8) * HF + 2 * ci)
                        = __floats2half2_rn(acc[mt][nt][2], acc[mt][nt][3]);
            }
            el0 += __shfl_xor_sync(0xFFFFFFFFu, el0, 1); el0 += __shfl_xor_sync(0xFFFFFFFFu, el0, 2);
            el1 += __shfl_xor_sync(0xFFFFFFFFu, el1, 1); el1 += __shfl_xor_sync(0xFFFFFFFFu, el1, 2);
            er0 += __shfl_xor_sync(0xFFFFFFFFu, er0, 1); er0 += __shfl_xor_sync(0xFFFFFFFFu, er0, 2);
            er1 += __shfl_xor_sync(0xFFFFFFFFu, er1, 1); er1 += __shfl_xor_sync(0xFFFFFFFFu, er1, 2);
            if (tig == 0) {
                if (r0 < V)     { g_el[r0 * HEADS + h] = el0;       g_er[r0 * HEADS + h] = er0; }
                if (r0 + 8 < V) { g_el[(r0 + 8) * HEADS + h] = el1; g_er[(r0 + 8) * HEADS + h] = er1; }
            }
        }
    } else {
        // residual + bias into out (fp32)
        int cb = (wcg - 4) * 32;
        float2 bv[4];
        #pragma unroll
        for (int nt = 0; nt < 4; nt++)
            bv[nt] = *reinterpret_cast<const float2*>(bias + cb + nt * 8 + 2 * tig);
        #pragma unroll
        for (int mt = 0; mt < 2; mt++) {
            int r0 = v0 + mbase + mt * 16 + gid;
            #pragma unroll
            for (int nt = 0; nt < 4; nt++) {
                int col = cb + nt * 8 + 2 * tig;
                if (r0 < V)
                    *reinterpret_cast<float2*>(out + (size_t)r0 * HF + col)
                        = make_float2(acc[mt][nt][0] + bv[nt].x, acc[mt][nt][1] + bv[nt].y);
                if (r0 + 8 < V)
                    *reinterpret_cast<float2*>(out + (size_t)(r0 + 8) * HF + col)
                        = make_float2(acc[mt][nt][2] + bv[nt].x, acc[mt][nt][3] + bv[nt].y);
            }
        }
    }
}

// ---------------- edge logits + exp + segment-sum denominator -----------
__global__ void k_edge(const float* __restrict__ ef, const int* __restrict__ src,
                       const int* __restrict__ dst, int E)
{
    __shared__ float swer[EDGE_IN * HEADS];
    if (threadIdx.x < EDGE_IN * HEADS) swer[threadIdx.x] = g_wer[threadIdx.x];
    __syncthreads();

    int i = blockIdx.x * blockDim.x + threadIdx.x;
    if (i >= E) return;

    float efv[16];
    #pragma unroll
    for (int q = 0; q < 4; q++) {
        float4 e4 = __ldg(reinterpret_cast<const float4*>(ef + (size_t)i * EDGE_IN + q * 4));
        efv[q * 4 + 0] = e4.x; efv[q * 4 + 1] = e4.y; efv[q * 4 + 2] = e4.z; efv[q * 4 + 3] = e4.w;
    }
    float ee0 = 0.f, ee1 = 0.f, ee2 = 0.f, ee3 = 0.f;
    #pragma unroll
    for (int j = 0; j < EDGE_IN; j++) {
        float e = efv[j];
        ee0 += e * swer[j * 4 + 0];
        ee1 += e * swer[j * 4 + 1];
        ee2 += e * swer[j * 4 + 2];
        ee3 += e * swer[j * 4 + 3];
    }

    int s = src[i], d = dst[i];
    float4 el4 = *reinterpret_cast<const float4*>(&g_el[s * HEADS]);
    float4 er4 = *reinterpret_cast<const float4*>(&g_er[d * HEADS]);

    float t0 = el4.x + er4.x + ee0;
    float t1 = el4.y + er4.y + ee1;
    float t2 = el4.z + er4.z + ee2;
    float t3 = el4.w + er4.w + ee3;
    t0 = (t0 >= 0.f) ? t0 : NEG_SLOPE * t0;
    t1 = (t1 >= 0.f) ? t1 : NEG_SLOPE * t1;
    t2 = (t2 >= 0.f) ? t2 : NEG_SLOPE * t2;
    t3 = (t3 >= 0.f) ? t3 : NEG_SLOPE * t3;
    // softmax is shift-invariant; logits are O(1) -> no max pass
    float x0 = __expf(t0), x1 = __expf(t1), x2 = __expf(t2), x3 = __expf(t3);

    *reinterpret_cast<float4*>(&g_ex[(size_t)i * HEADS]) = make_float4(x0, x1, x2, x3);

    float* ep = &g_esum[d * HEADS];
    asm volatile("red.global.add.v4.f32 [%0], {%1,%2,%3,%4};"
                 :: "l"(ep), "f"(x0), "f"(x1), "f"(x2), "f"(x3) : "memory");
}

// ---------------- aggregation: one block per dst, fp16 ft gathers -------
__global__ void __launch_bounds__(128) k_agg(const int* __restrict__ src,
                                             float* __restrict__ out, int V)
{
    __shared__ int   s_src[ETILE];
    __shared__ float s_a[HEADS][ETILE];
    __shared__ float4 s_red[3][32];

    int v = blockIdx.x;
    int t = threadIdx.x, w = t >> 5, lane = t & 31;
    int beg = g_rowptr[v], end = g_rowptr[v + 1];
    if (end <= beg) return;

    float4 es = *reinterpret_cast<const float4*>(&g_esum[v * HEADS]);
    float iv0 = 1.0f / es.x, iv1 = 1.0f / es.y, iv2 = 1.0f / es.z, iv3 = 1.0f / es.w;

    int h = lane >> 3;
    float4 acc = make_float4(0.f, 0.f, 0.f, 0.f);

    for (int pos = beg; pos < end; pos += ETILE) {
        int cnt = min(ETILE, end - pos);
        __syncthreads();
        if (t < cnt) {
            int eid = g_csr[pos + t];
            s_src[t] = src[eid];
            float4 ex = *reinterpret_cast<const float4*>(&g_ex[(size_t)eid * HEADS]);
            s_a[0][t] = ex.x * iv0;
            s_a[1][t] = ex.y * iv1;
            s_a[2][t] = ex.z * iv2;
            s_a[3][t] = ex.w * iv3;
        }
        __syncthreads();
        #pragma unroll 2
        for (int j = w; j < cnt; j += 4) {
            int sv = s_src[j];
            float a = s_a[h][j];
            uint2 u = __ldg(reinterpret_cast<const uint2*>(g_fth + (size_t)sv * HF + lane * 4));
            float2 f01 = __half22float2(*reinterpret_cast<__half2*>(&u.x));
            float2 f23 = __half22float2(*reinterpret_cast<__half2*>(&u.y));
            acc.x += a * f01.x; acc.y += a * f01.y; acc.z += a * f23.x; acc.w += a * f23.y;
        }
    }

    if (w > 0) s_red[w - 1][lane] = acc;
    __syncthreads();
    if (w == 0) {
        acc.x += s_red[0][lane].x + s_red[1][lane].x + s_red[2][lane].x;
        acc.y += s_red[0][lane].y + s_red[1][lane].y + s_red[2][lane].y;
        acc.z += s_red[0][lane].z + s_red[1][lane].z + s_red[2][lane].z;
        acc.w += s_red[0][lane].w + s_red[1][lane].w + s_red[2][lane].w;
        float4* op = reinterpret_cast<float4*>(out + (size_t)v * HF + lane * 4);
        float4 o = *op;
        o.x += acc.x; o.y += acc.y; o.z += acc.z; o.w += acc.w;
        *op = o;
    }
}

// ---------------- launch with forked capture streams (round-6 schedule) --
static cudaStream_t g_s2 = nullptr;
static cudaEvent_t g_evFork = nullptr, g_evJoin = nullptr, g_evZ = nullptr;

extern "C" void kernel_launch(void* const* d_in, const int* in_sizes, int n_in,
                              void* d_out, int out_size)
{
    const float* nf   = (const float*)d_in[0];
    const float* ef   = (const float*)d_in[1];
    const int*   src  = (const int*)d_in[2];
    const int*   dst  = (const int*)d_in[3];
    const float* Wn   = (const float*)d_in[4];
    const float* We   = (const float*)d_in[5];
    const float* al   = (const float*)d_in[6];
    const float* ar   = (const float*)d_in[7];
    const float* ae   = (const float*)d_in[8];
    const float* Wr   = (const float*)d_in[9];
    const float* bias = (const float*)d_in[10];
    float* out = (float*)d_out;

    int V = in_sizes[0] / NODE_IN;
    int E = in_sizes[2];
    if (V > MAXV) V = MAXV;
    if (E > MAXE) E = MAXE;

    if (!g_s2) {
        cudaStreamCreateWithFlags(&g_s2, cudaStreamNonBlocking);
        cudaEventCreateWithFlags(&g_evFork, cudaEventDisableTiming);
        cudaEventCreateWithFlags(&g_evJoin, cudaEventDisableTiming);
        cudaEventCreateWithFlags(&g_evZ, cudaEventDisableTiming);
    }

    const int smemProj = PROJ_ROWS * XS_LD * sizeof(float);   // ~33.8 KB
    int nch = (V + 1023) / 1024;

    cudaEventRecord(g_evFork, 0);
    cudaStreamWaitEvent(g_s2, g_evFork, 0);

    k_fold<<<(NODE_IN * HF / 2 + 255) / 256, 256>>>(We, ae, Wn, Wr);  // #1 main
    k_zero<<<(V * HEADS + 255) / 256, 256, 0, g_s2>>>(V);             // #2 side
    cudaEventRecord(g_evZ, g_s2);
    k_hist<<<(E + 255) / 256, 256, 0, g_s2>>>(dst, E);                // #3 side
    k_nodeproj<<<(V + PROJ_ROWS - 1) / PROJ_ROWS, 512, smemProj>>>(nf, bias, al, ar, out, V);  // #4 main (profiled)
    k_scan1<<<nch, 1024, 0, g_s2>>>(V);                               // #5 side
    k_scan3<<<nch, 1024, 0, g_s2>>>(V);                               // #6 side
    k_fill<<<(E + 255) / 256, 256, 0, g_s2>>>(dst, E);                // #7 side
    cudaEventRecord(g_evJoin, g_s2);

    cudaStreamWaitEvent(0, g_evZ, 0);
    k_edge<<<(E + 127) / 128, 128>>>(ef, src, dst, E);                // #8 main

    cudaStreamWaitEvent(0, g_evJoin, 0);
    k_agg<<<V, 128>>>(src, out, V);                                   // #9 main
}

// round 9
// speedup vs baseline: 1.9215x; 1.2752x over previous
#include <cuda_runtime.h>
#include <cuda_fp16.h>
#include <cstdint>

#define MAXV 50000
#define MAXE 800000
#define NODE_IN 128
#define EDGE_IN 16
#define HF 128
#define HEADS 4
#define OUTF 32
#define NEG_SLOPE 0.2f
#define PROJ_ROWS 64
#define XS_LD 132   // padded smem stride (floats) -> conflict-free A frags

// ---------------- device scratch ----------------
__device__ __half g_fth[MAXV * HF];     // projected node feats (fp16)
__device__ __half g_exh[MAXE * HEADS];  // exp(logit) per edge (fp16 x4)
__device__ float g_el[MAXV * HEADS];
__device__ float g_er[MAXV * HEADS];
__device__ int   g_deg[MAXV];
__device__ int   g_incl[MAXV];
__device__ int   g_bsum[64];
__device__ int   g_rowptr[MAXV + 1];
__device__ int   g_cursor[MAXV];
__device__ int   g_csr[MAXE];
__device__ float g_wer[EDGE_IN * HEADS];
// pair-packed tf32 weights: index ((ks*HF + col)*4 + tig) -> (k=ks*8+tig, k+4)
__device__ uint2 g_wnr2[(NODE_IN / 8) * HF * 4];
__device__ uint2 g_wrr2[(NODE_IN / 8) * HF * 4];

__device__ __forceinline__ unsigned tf32r(float x) {
    unsigned u;
    asm("cvt.rna.tf32.f32 %0, %1;" : "=r"(u) : "f"(x));
    return u;
}

__device__ __forceinline__ void mma_tf32(float* d, const unsigned* a, const unsigned* b) {
    asm volatile(
        "mma.sync.aligned.m16n8k8.row.col.f32.tf32.tf32.f32 "
        "{%0,%1,%2,%3}, {%4,%5,%6,%7}, {%8,%9}, {%0,%1,%2,%3};"
        : "+f"(d[0]), "+f"(d[1]), "+f"(d[2]), "+f"(d[3])
        : "r"(a[0]), "r"(a[1]), "r"(a[2]), "r"(a[3]), "r"(b[0]), "r"(b[1]));
}

// ---------------- CSR-build kernels (side stream) ----------------
__global__ void k_zero(int V) {
    int i = blockIdx.x * blockDim.x + threadIdx.x;
    if (i < V) g_deg[i] = 0;
}

__global__ void k_hist(const int* __restrict__ dst, int E) {
    int i = blockIdx.x * blockDim.x + threadIdx.x;
    if (i < E) atomicAdd(&g_deg[dst[i]], 1);
}

__global__ void k_scan1(int V) {
    __shared__ int wsum[32];
    int b = blockIdx.x, t = threadIdx.x;
    int i = b * 1024 + t;
    int val = (i < V) ? g_deg[i] : 0;
    int lane = t & 31, wid = t >> 5;
    int x = val;
    #pragma unroll
    for (int o = 1; o < 32; o <<= 1) {
        int y = __shfl_up_sync(0xFFFFFFFFu, x, o);
        if (lane >= o) x += y;
    }
    if (lane == 31) wsum[wid] = x;
    __syncthreads();
    if (wid == 0) {
        int s = wsum[lane];
        #pragma unroll
        for (int o = 1; o < 32; o <<= 1) {
            int y = __shfl_up_sync(0xFFFFFFFFu, s, o);
            if (lane >= o) s += y;
        }
        wsum[lane] = s;
    }
    __syncthreads();
    int incl = x + (wid > 0 ? wsum[wid - 1] : 0);
    if (i < V) g_incl[i] = incl;
    if (t == 1023) g_bsum[b] = incl;
}

__global__ void k_scan3(int V) {
    __shared__ int soff;
    int b = blockIdx.x, t = threadIdx.x;
    if (t < 32) {
        int s = 0;
        for (int j = t; j < b; j += 32) s += g_bsum[j];
        #pragma unroll
        for (int o = 16; o > 0; o >>= 1) s += __shfl_xor_sync(0xFFFFFFFFu, s, o);
        if (t == 0) soff = s;
    }
    __syncthreads();
    int i = b * 1024 + t;
    if (i < V) {
        int incl = g_incl[i] + soff;
        g_rowptr[i + 1] = incl;
        g_cursor[i] = incl - g_deg[i];
        if (i == 0) g_rowptr[0] = 0;
    }
}

__global__ void k_fill(const int* __restrict__ dst, int E) {
    int i = blockIdx.x * blockDim.x + threadIdx.x;
    if (i < E) {
        int pos = atomicAdd(&g_cursor[dst[i]], 1);
        g_csr[pos] = i;
    }
}

// ---------------- fold + tf32 weight rounding into pair-packed layout ----
__global__ void k_fold(const float* __restrict__ We, const float* __restrict__ ae,
                       const float* __restrict__ Wn, const float* __restrict__ Wr) {
    int i = blockIdx.x * blockDim.x + threadIdx.x;
    int NP = (NODE_IN / 8) * HF * 4;     // 8192
    if (i < NP) {
        int ks  = i >> 9;                // /(HF*4)
        int col = (i >> 2) & (HF - 1);
        int tig = i & 3;
        int k0 = ks * 8 + tig;
        g_wnr2[i] = make_uint2(tf32r(Wn[(size_t)k0 * HF + col]),
                               tf32r(Wn[(size_t)(k0 + 4) * HF + col]));
        g_wrr2[i] = make_uint2(tf32r(Wr[(size_t)k0 * HF + col]),
                               tf32r(Wr[(size_t)(k0 + 4) * HF + col]));
    }
    if (blockIdx.x == 0 && threadIdx.x < EDGE_IN * HEADS) {
        int t = threadIdx.x;
        int j = t >> 2, h = t & 3;
        float s = 0.0f;
        #pragma unroll
        for (int f = 0; f < OUTF; f++)
            s += We[j * HF + h * OUTF + f] * ae[h * OUTF + f];
        g_wer[j * HEADS + h] = s;
    }
}

// ---------------- node projection via TF32 HMMA ----------------
__global__ void __launch_bounds__(512) k_nodeproj(
    const float* __restrict__ nf, const float* __restrict__ bias,
    const float* __restrict__ al, const float* __restrict__ ar,
    float* __restrict__ out, int V)
{
    extern __shared__ float xs[];   // [64][XS_LD]
    int v0 = blockIdx.x * PROJ_ROWS;
    int tid = threadIdx.x;

    #pragma unroll
    for (int i = 0; i < 4; i++) {
        int idx = tid + i * 512;
        int r = idx >> 5;
        int c4 = idx & 31;
        int v = v0 + r;
        float4 val = make_float4(0.f, 0.f, 0.f, 0.f);
        if (v < V) val = *reinterpret_cast<const float4*>(nf + (size_t)v * NODE_IN + c4 * 4);
        val.x = __uint_as_float(tf32r(val.x));
        val.y = __uint_as_float(tf32r(val.y));
        val.z = __uint_as_float(tf32r(val.z));
        val.w = __uint_as_float(tf32r(val.w));
        *reinterpret_cast<float4*>(&xs[r * XS_LD + c4 * 4]) = val;
    }
    __syncthreads();

    int lane = tid & 31;
    int warp = tid >> 5;
    int wrow = warp & 1;
    int wcg  = warp >> 1;
    int tig  = lane & 3;
    int gid  = lane >> 2;

    const uint2* B2 = (wcg < 4) ? g_wnr2 : g_wrr2;
    int nb = (wcg & 3) * 32;
    int mbase = wrow * 32;

    float acc[2][4][4];
    #pragma unroll
    for (int mt = 0; mt < 2; mt++)
        #pragma unroll
        for (int nt = 0; nt < 4; nt++)
            #pragma unroll
            for (int q = 0; q < 4; q++) acc[mt][nt][q] = 0.f;

    #pragma unroll 4
    for (int ks = 0; ks < 16; ks++) {
        int kb = ks * 8;
        unsigned a[2][4];
        #pragma unroll
        for (int mt = 0; mt < 2; mt++) {
            int r0 = mbase + mt * 16 + gid;
            a[mt][0] = __float_as_uint(xs[r0 * XS_LD + kb + tig]);
            a[mt][1] = __float_as_uint(xs[(r0 + 8) * XS_LD + kb + tig]);
            a[mt][2] = __float_as_uint(xs[r0 * XS_LD + kb + tig + 4]);
            a[mt][3] = __float_as_uint(xs[(r0 + 8) * XS_LD + kb + tig + 4]);
        }
        unsigned b[4][2];
        #pragma unroll
        for (int nt = 0; nt < 4; nt++) {
            int col = nb + nt * 8 + gid;
            uint2 bp = __ldg(&B2[(ks * HF + col) * 4 + tig]);
            b[nt][0] = bp.x;
            b[nt][1] = bp.y;
        }
        #pragma unroll
        for (int mt = 0; mt < 2; mt++)
            #pragma unroll
            for (int nt = 0; nt < 4; nt++)
                mma_tf32(acc[mt][nt], a[mt], b[nt]);
    }

    if (wcg < 4) {
        int h = wcg;
        float2 alf[4], arf[4];
        #pragma unroll
        for (int nt = 0; nt < 4; nt++) {
            alf[nt] = *reinterpret_cast<const float2*>(al + h * OUTF + nt * 8 + 2 * tig);
            arf[nt] = *reinterpret_cast<const float2*>(ar + h * OUTF + nt * 8 + 2 * tig);
        }
        #pragma unroll
        for (int mt = 0; mt < 2; mt++) {
            int r0 = v0 + mbase + mt * 16 + gid;
            float el0 = 0.f, el1 = 0.f, er0 = 0.f, er1 = 0.f;
            #pragma unroll
            for (int nt = 0; nt < 4; nt++) {
                el0 += acc[mt][nt][0] * alf[nt].x + acc[mt][nt][1] * alf[nt].y;
                el1 += acc[mt][nt][2] * alf[nt].x + acc[mt][nt][3] * alf[nt].y;
                er0 += acc[mt][nt][0] * arf[nt].x + acc[mt][nt][1] * arf[nt].y;
                er1 += acc[mt][nt][2] * arf[nt].x + acc[mt][nt][3] * arf[nt].y;
                int ci = h * 16 + nt * 4 + tig;   // half2 col index
                if (r0 < V)
                    *reinterpret_cast<__half2*>(g_fth + (size_t)r0 * HF + 2 * ci)
                        = __floats2half2_rn(acc[mt][nt][0], acc[mt][nt][1]);
                if (r0 + 8 < V)
                    *reinterpret_cast<__half2*>(g_fth + (size_t)(r0 + 8) * HF + 2 * ci)
                        = __floats2half2_rn(acc[mt][nt][2], acc[mt][nt][3]);
            }
            el0 += __shfl_xor_sync(0xFFFFFFFFu, el0, 1); el0 += __shfl_xor_sync(0xFFFFFFFFu, el0, 2);
            el1 += __shfl_xor_sync(0xFFFFFFFFu, el1, 1); el1 += __shfl_xor_sync(0xFFFFFFFFu, el1, 2);
            er0 += __shfl_xor_sync(0xFFFFFFFFu, er0, 1); er0 += __shfl_xor_sync(0xFFFFFFFFu, er0, 2);
            er1 += __shfl_xor_sync(0xFFFFFFFFu, er1, 1); er1 += __shfl_xor_sync(0xFFFFFFFFu, er1, 2);
            if (tig == 0) {
                if (r0 < V)     { g_el[r0 * HEADS + h] = el0;       g_er[r0 * HEADS + h] = er0; }
                if (r0 + 8 < V) { g_el[(r0 + 8) * HEADS + h] = el1; g_er[(r0 + 8) * HEADS + h] = er1; }
            }
        }
    } else {
        int cb = (wcg - 4) * 32;
        float2 bv[4];
        #pragma unroll
        for (int nt = 0; nt < 4; nt++)
            bv[nt] = *reinterpret_cast<const float2*>(bias + cb + nt * 8 + 2 * tig);
        #pragma unroll
        for (int mt = 0; mt < 2; mt++) {
            int r0 = v0 + mbase + mt * 16 + gid;
            #pragma unroll
            for (int nt = 0; nt < 4; nt++) {
                int col = cb + nt * 8 + 2 * tig;
                if (r0 < V)
                    *reinterpret_cast<float2*>(out + (size_t)r0 * HF + col)
                        = make_float2(acc[mt][nt][0] + bv[nt].x, acc[mt][nt][1] + bv[nt].y);
                if (r0 + 8 < V)
                    *reinterpret_cast<float2*>(out + (size_t)(r0 + 8) * HF + col)
                        = make_float2(acc[mt][nt][2] + bv[nt].x, acc[mt][nt][3] + bv[nt].y);
            }
        }
    }
}

// ---------------- edge logits + exp (fp16 out, no atomics) ---------------
__global__ void k_edge(const float* __restrict__ ef, const int* __restrict__ src,
                       const int* __restrict__ dst, int E)
{
    __shared__ float swer[EDGE_IN * HEADS];
    if (threadIdx.x < EDGE_IN * HEADS) swer[threadIdx.x] = g_wer[threadIdx.x];
    __syncthreads();

    int i = blockIdx.x * blockDim.x + threadIdx.x;
    if (i >= E) return;

    float efv[16];
    #pragma unroll
    for (int q = 0; q < 4; q++) {
        float4 e4 = __ldg(reinterpret_cast<const float4*>(ef + (size_t)i * EDGE_IN + q * 4));
        efv[q * 4 + 0] = e4.x; efv[q * 4 + 1] = e4.y; efv[q * 4 + 2] = e4.z; efv[q * 4 + 3] = e4.w;
    }
    float ee0 = 0.f, ee1 = 0.f, ee2 = 0.f, ee3 = 0.f;
    #pragma unroll
    for (int j = 0; j < EDGE_IN; j++) {
        float e = efv[j];
        ee0 += e * swer[j * 4 + 0];
        ee1 += e * swer[j * 4 + 1];
        ee2 += e * swer[j * 4 + 2];
        ee3 += e * swer[j * 4 + 3];
    }

    int s = src[i], d = dst[i];
    float4 el4 = *reinterpret_cast<const float4*>(&g_el[s * HEADS]);
    float4 er4 = *reinterpret_cast<const float4*>(&g_er[d * HEADS]);

    float t0 = el4.x + er4.x + ee0;
    float t1 = el4.y + er4.y + ee1;
    float t2 = el4.z + er4.z + ee2;
    float t3 = el4.w + er4.w + ee3;
    t0 = (t0 >= 0.f) ? t0 : NEG_SLOPE * t0;
    t1 = (t1 >= 0.f) ? t1 : NEG_SLOPE * t1;
    t2 = (t2 >= 0.f) ? t2 : NEG_SLOPE * t2;
    t3 = (t3 >= 0.f) ? t3 : NEG_SLOPE * t3;
    // softmax is shift-invariant; logits are O(1) -> no max pass, and the
    // denominator is accumulated inside k_agg (distributive), so no atomics.
    __half2 h01 = __floats2half2_rn(__expf(t0), __expf(t1));
    __half2 h23 = __floats2half2_rn(__expf(t2), __expf(t3));
    uint2 pk;
    pk.x = *reinterpret_cast<unsigned*>(&h01);
    pk.y = *reinterpret_cast<unsigned*>(&h23);
    *reinterpret_cast<uint2*>(g_exh + (size_t)i * HEADS) = pk;
}

// ---------------- aggregation: one warp per dst ----------------
// Batched index staging: 32 lanes gather eid/src/ex for up to 32 edges at
// once (full MLP), then the inner loop is independent 8B ft gathers + shfl.
// Softmax denominator accumulated locally; single divide at the end.
__global__ void __launch_bounds__(256) k_agg(const int* __restrict__ src,
                                             float* __restrict__ out, int V)
{
    int gw = (blockIdx.x * 256 + threadIdx.x) >> 5;
    int lane = threadIdx.x & 31;
    if (gw >= V) return;
    int v = gw;
    int beg = g_rowptr[v], end = g_rowptr[v + 1];
    if (end <= beg) return;   // out already holds residual + bias

    int h = lane >> 3;
    float4 acc = make_float4(0.f, 0.f, 0.f, 0.f);
    float sacc = 0.0f;

    for (int base = beg; base < end; base += 32) {
        int n = end - base; if (n > 32) n = 32;
        int eid = 0, sv = 0;
        uint2 exu = make_uint2(0, 0);
        if (lane < n) {
            eid = g_csr[base + lane];
            sv  = __ldg(src + eid);
            exu = *reinterpret_cast<const uint2*>(g_exh + (size_t)eid * HEADS);
        }
        #pragma unroll 4
        for (int e = 0; e < n; e++) {
            int sve = __shfl_sync(0xFFFFFFFFu, sv, e);
            unsigned w0 = __shfl_sync(0xFFFFFFFFu, exu.x, e);
            unsigned w1 = __shfl_sync(0xFFFFFFFFu, exu.y, e);
            unsigned wh = (h < 2) ? w0 : w1;
            __half2 hp = *reinterpret_cast<__half2*>(&wh);
            float a = (h & 1) ? __high2float(hp) : __low2float(hp);
            uint2 u = __ldg(reinterpret_cast<const uint2*>(g_fth + (size_t)sve * HF + lane * 4));
            float2 f01 = __half22float2(*reinterpret_cast<__half2*>(&u.x));
            float2 f23 = __half22float2(*reinterpret_cast<__half2*>(&u.y));
            acc.x += a * f01.x; acc.y += a * f01.y;
            acc.z += a * f23.x; acc.w += a * f23.y;
            sacc += a;
        }
    }

    float inv = 1.0f / sacc;
    float4* op = reinterpret_cast<float4*>(out + (size_t)v * HF + lane * 4);
    float4 o = *op;
    o.x += acc.x * inv; o.y += acc.y * inv; o.z += acc.z * inv; o.w += acc.w * inv;
    *op = o;
}

// ---------------- launch with forked capture streams ----------------
static cudaStream_t g_s2 = nullptr;
static cudaEvent_t g_evFork = nullptr, g_evJoin = nullptr;

extern "C" void kernel_launch(void* const* d_in, const int* in_sizes, int n_in,
                              void* d_out, int out_size)
{
    const float* nf   = (const float*)d_in[0];
    const float* ef   = (const float*)d_in[1];
    const int*   src  = (const int*)d_in[2];
    const int*   dst  = (const int*)d_in[3];
    const float* Wn   = (const float*)d_in[4];
    const float* We   = (const float*)d_in[5];
    const float* al   = (const float*)d_in[6];
    const float* ar   = (const float*)d_in[7];
    const float* ae   = (const float*)d_in[8];
    const float* Wr   = (const float*)d_in[9];
    const float* bias = (const float*)d_in[10];
    float* out = (float*)d_out;

    int V = in_sizes[0] / NODE_IN;
    int E = in_sizes[2];
    if (V > MAXV) V = MAXV;
    if (E > MAXE) E = MAXE;

    if (!g_s2) {
        cudaStreamCreateWithFlags(&g_s2, cudaStreamNonBlocking);
        cudaEventCreateWithFlags(&g_evFork, cudaEventDisableTiming);
        cudaEventCreateWithFlags(&g_evJoin, cudaEventDisableTiming);
    }

    const int smemProj = PROJ_ROWS * XS_LD * sizeof(float);   // ~33.8 KB
    int nch = (V + 1023) / 1024;

    cudaEventRecord(g_evFork, 0);
    cudaStreamWaitEvent(g_s2, g_evFork, 0);

    k_fold<<<(NODE_IN * HF / 2 + 255) / 256, 256>>>(We, ae, Wn, Wr);  // #1 main
    k_zero<<<(V + 255) / 256, 256, 0, g_s2>>>(V);                     // #2 side
    k_hist<<<(E + 255) / 256, 256, 0, g_s2>>>(dst, E);                // #3 side
    k_nodeproj<<<(V + PROJ_ROWS - 1) / PROJ_ROWS, 512, smemProj>>>(nf, bias, al, ar, out, V);  // #4 main (profiled)
    k_scan1<<<nch, 1024, 0, g_s2>>>(V);                               // #5 side
    k_scan3<<<nch, 1024, 0, g_s2>>>(V);                               // #6 side
    k_fill<<<(E + 255) / 256, 256, 0, g_s2>>>(dst, E);                // #7 side
    cudaEventRecord(g_evJoin, g_s2);

    k_edge<<<(E + 127) / 128, 128>>>(ef, src, dst, E);                // #8 main

    cudaStreamWaitEvent(0, g_evJoin, 0);
    k_agg<<<(V * 32 + 255) / 256, 256>>>(src, out, V);                // #9 main
}

// round 10
// speedup vs baseline: 2.0059x; 1.0439x over previous
#include <cuda_runtime.h>
#include <cuda_fp16.h>
#include <cstdint>

#define MAXV 50000
#define MAXE 800000
#define NODE_IN 128
#define EDGE_IN 16
#define HF 128
#define HEADS 4
#define OUTF 32
#define NEG_SLOPE 0.2f
#define PROJ_ROWS 64
#define XS_LD 132   // padded smem stride (floats) -> conflict-free A frags

// ---------------- device scratch ----------------
__device__ __half g_fth[MAXV * HF];     // projected node feats (fp16)
__device__ __half g_exh[MAXE * HEADS];  // exp(logit) per edge (fp16 x4)
__device__ float g_el[MAXV * HEADS];
__device__ float g_er[MAXV * HEADS];
__device__ int   g_deg[MAXV];
__device__ int   g_incl[MAXV];
__device__ int   g_bsum[64];
__device__ int   g_rowptr[MAXV + 1];
__device__ int   g_cursor[MAXV];
__device__ int   g_csr[MAXE];
__device__ float g_wer[EDGE_IN * HEADS];
// pair-packed tf32 weights: index ((ks*HF + col)*4 + tig) -> (k=ks*8+tig, k+4)
__device__ uint2 g_wnr2[(NODE_IN / 8) * HF * 4];
__device__ uint2 g_wrr2[(NODE_IN / 8) * HF * 4];

__device__ __forceinline__ unsigned tf32r(float x) {
    unsigned u;
    asm("cvt.rna.tf32.f32 %0, %1;" : "=r"(u) : "f"(x));
    return u;
}

__device__ __forceinline__ void mma_tf32(float* d, const unsigned* a, const unsigned* b) {
    asm volatile(
        "mma.sync.aligned.m16n8k8.row.col.f32.tf32.tf32.f32 "
        "{%0,%1,%2,%3}, {%4,%5,%6,%7}, {%8,%9}, {%0,%1,%2,%3};"
        : "+f"(d[0]), "+f"(d[1]), "+f"(d[2]), "+f"(d[3])
        : "r"(a[0]), "r"(a[1]), "r"(a[2]), "r"(a[3]), "r"(b[0]), "r"(b[1]));
}

// ---------------- CSR-build kernels (side stream) ----------------
__global__ void k_zero(int V) {
    int i = blockIdx.x * blockDim.x + threadIdx.x;
    if (i < V) g_deg[i] = 0;
}

__global__ void k_hist(const int* __restrict__ dst, int E) {
    int i = blockIdx.x * blockDim.x + threadIdx.x;
    if (i < E) atomicAdd(&g_deg[dst[i]], 1);
}

__global__ void k_scan1(int V) {
    __shared__ int wsum[32];
    int b = blockIdx.x, t = threadIdx.x;
    int i = b * 1024 + t;
    int val = (i < V) ? g_deg[i] : 0;
    int lane = t & 31, wid = t >> 5;
    int x = val;
    #pragma unroll
    for (int o = 1; o < 32; o <<= 1) {
        int y = __shfl_up_sync(0xFFFFFFFFu, x, o);
        if (lane >= o) x += y;
    }
    if (lane == 31) wsum[wid] = x;
    __syncthreads();
    if (wid == 0) {
        int s = wsum[lane];
        #pragma unroll
        for (int o = 1; o < 32; o <<= 1) {
            int y = __shfl_up_sync(0xFFFFFFFFu, s, o);
            if (lane >= o) s += y;
        }
        wsum[lane] = s;
    }
    __syncthreads();
    int incl = x + (wid > 0 ? wsum[wid - 1] : 0);
    if (i < V) g_incl[i] = incl;
    if (t == 1023) g_bsum[b] = incl;
}

__global__ void k_scan3(int V) {
    __shared__ int soff;
    int b = blockIdx.x, t = threadIdx.x;
    if (t < 32) {
        int s = 0;
        for (int j = t; j < b; j += 32) s += g_bsum[j];
        #pragma unroll
        for (int o = 16; o > 0; o >>= 1) s += __shfl_xor_sync(0xFFFFFFFFu, s, o);
        if (t == 0) soff = s;
    }
    __syncthreads();
    int i = b * 1024 + t;
    if (i < V) {
        int incl = g_incl[i] + soff;
        g_rowptr[i + 1] = incl;
        g_cursor[i] = incl - g_deg[i];
        if (i == 0) g_rowptr[0] = 0;
    }
}

__global__ void k_fill(const int* __restrict__ dst, int E) {
    int i = blockIdx.x * blockDim.x + threadIdx.x;
    if (i < E) {
        int pos = atomicAdd(&g_cursor[dst[i]], 1);
        g_csr[pos] = i;
    }
}

// ---------------- fold + tf32 weight rounding into pair-packed layout ----
__global__ void k_fold(const float* __restrict__ We, const float* __restrict__ ae,
                       const float* __restrict__ Wn, const float* __restrict__ Wr) {
    int i = blockIdx.x * blockDim.x + threadIdx.x;
    int NP = (NODE_IN / 8) * HF * 4;     // 8192
    if (i < NP) {
        int ks  = i >> 9;                // /(HF*4)
        int col = (i >> 2) & (HF - 1);
        int tig = i & 3;
        int k0 = ks * 8 + tig;
        g_wnr2[i] = make_uint2(tf32r(Wn[(size_t)k0 * HF + col]),
                               tf32r(Wn[(size_t)(k0 + 4) * HF + col]));
        g_wrr2[i] = make_uint2(tf32r(Wr[(size_t)k0 * HF + col]),
                               tf32r(Wr[(size_t)(k0 + 4) * HF + col]));
    }
    if (blockIdx.x == 0 && threadIdx.x < EDGE_IN * HEADS) {
        int t = threadIdx.x;
        int j = t >> 2, h = t & 3;
        float s = 0.0f;
        #pragma unroll
        for (int f = 0; f < OUTF; f++)
            s += We[j * HF + h * OUTF + f] * ae[h * OUTF + f];
        g_wer[j * HEADS + h] = s;
    }
}

// ---------------- node projection via TF32 HMMA ----------------
// 256 threads, 64-row tile. Warp grid: 2 row halves x 4 col groups of 64.
// Warp tile: 2 m16 x 8 n8. Halves redundant A-fragment LDS traffic vs the
// 8-colgroup config (4 warps share each row instead of 8).
// Col groups 0,1 -> ft cols 0..63 / 64..127 (2 heads each, fused el/er);
// col groups 2,3 -> residual out cols 0..63 / 64..127 + bias.
__global__ void __launch_bounds__(256, 2) k_nodeproj(
    const float* __restrict__ nf, const float* __restrict__ bias,
    const float* __restrict__ al, const float* __restrict__ ar,
    float* __restrict__ out, int V)
{
    extern __shared__ float xs[];   // [64][XS_LD]
    int v0 = blockIdx.x * PROJ_ROWS;
    int tid = threadIdx.x;

    #pragma unroll
    for (int i = 0; i < 8; i++) {
        int idx = tid + i * 256;          // 0..2047 float4 slots
        int r = idx >> 5;                 // row 0..63
        int c4 = idx & 31;
        int v = v0 + r;
        float4 val = make_float4(0.f, 0.f, 0.f, 0.f);
        if (v < V) val = *reinterpret_cast<const float4*>(nf + (size_t)v * NODE_IN + c4 * 4);
        val.x = __uint_as_float(tf32r(val.x));
        val.y = __uint_as_float(tf32r(val.y));
        val.z = __uint_as_float(tf32r(val.z));
        val.w = __uint_as_float(tf32r(val.w));
        *reinterpret_cast<float4*>(&xs[r * XS_LD + c4 * 4]) = val;
    }
    __syncthreads();

    int lane = tid & 31;
    int warp = tid >> 5;                  // 0..7
    int wrow = warp & 1;                  // row half (32 rows)
    int wcg  = warp >> 1;                 // col group 0..3 (64 cols each)
    int tig  = lane & 3;
    int gid  = lane >> 2;

    const uint2* B2 = (wcg < 2) ? g_wnr2 : g_wrr2;
    int nb = (wcg & 1) * 64;
    int mbase = wrow * 32;

    float acc[2][8][4];
    #pragma unroll
    for (int mt = 0; mt < 2; mt++)
        #pragma unroll
        for (int nt = 0; nt < 8; nt++)
            #pragma unroll
            for (int q = 0; q < 4; q++) acc[mt][nt][q] = 0.f;

    #pragma unroll 2
    for (int ks = 0; ks < 16; ks++) {
        int kb = ks * 8;
        unsigned a[2][4];
        #pragma unroll
        for (int mt = 0; mt < 2; mt++) {
            int r0 = mbase + mt * 16 + gid;
            a[mt][0] = __float_as_uint(xs[r0 * XS_LD + kb + tig]);
            a[mt][1] = __float_as_uint(xs[(r0 + 8) * XS_LD + kb + tig]);
            a[mt][2] = __float_as_uint(xs[r0 * XS_LD + kb + tig + 4]);
            a[mt][3] = __float_as_uint(xs[(r0 + 8) * XS_LD + kb + tig + 4]);
        }
        unsigned b[8][2];
        #pragma unroll
        for (int nt = 0; nt < 8; nt++) {
            int col = nb + nt * 8 + gid;
            uint2 bp = __ldg(&B2[(ks * HF + col) * 4 + tig]);
            b[nt][0] = bp.x;
            b[nt][1] = bp.y;
        }
        #pragma unroll
        for (int mt = 0; mt < 2; mt++)
            #pragma unroll
            for (int nt = 0; nt < 8; nt++)
                mma_tf32(acc[mt][nt], a[mt], b[nt]);
    }

    if (wcg < 2) {
        // ft (fp16) store + fused el/er; heads h0 = wcg*2 (nt 0..3), h0+1 (nt 4..7)
        float2 alf[8], arf[8];
        #pragma unroll
        for (int nt = 0; nt < 8; nt++) {
            int h = wcg * 2 + (nt >> 2);
            int off = h * OUTF + (nt & 3) * 8 + 2 * tig;
            alf[nt] = *reinterpret_cast<const float2*>(al + off);
            arf[nt] = *reinterpret_cast<const float2*>(ar + off);
        }
        #pragma unroll
        for (int mt = 0; mt < 2; mt++) {
            int r0 = v0 + mbase + mt * 16 + gid;
            float el0[2] = {0.f, 0.f}, el1[2] = {0.f, 0.f};
            float er0[2] = {0.f, 0.f}, er1[2] = {0.f, 0.f};
            #pragma unroll
            for (int nt = 0; nt < 8; nt++) {
                int hh = nt >> 2;
                el0[hh] += acc[mt][nt][0] * alf[nt].x + acc[mt][nt][1] * alf[nt].y;
                el1[hh] += acc[mt][nt][2] * alf[nt].x + acc[mt][nt][3] * alf[nt].y;
                er0[hh] += acc[mt][nt][0] * arf[nt].x + acc[mt][nt][1] * arf[nt].y;
                er1[hh] += acc[mt][nt][2] * arf[nt].x + acc[mt][nt][3] * arf[nt].y;
                int col = wcg * 64 + nt * 8 + 2 * tig;
                if (r0 < V)
                    *reinterpret_cast<__half2*>(g_fth + (size_t)r0 * HF + col)
                        = __floats2half2_rn(acc[mt][nt][0], acc[mt][nt][1]);
                if (r0 + 8 < V)
                    *reinterpret_cast<__half2*>(g_fth + (size_t)(r0 + 8) * HF + col)
                        = __floats2half2_rn(acc[mt][nt][2], acc[mt][nt][3]);
            }
            #pragma unroll
            for (int hh = 0; hh < 2; hh++) {
                float a0 = el0[hh], a1 = el1[hh], b0 = er0[hh], b1 = er1[hh];
                a0 += __shfl_xor_sync(0xFFFFFFFFu, a0, 1); a0 += __shfl_xor_sync(0xFFFFFFFFu, a0, 2);
                a1 += __shfl_xor_sync(0xFFFFFFFFu, a1, 1); a1 += __shfl_xor_sync(0xFFFFFFFFu, a1, 2);
                b0 += __shfl_xor_sync(0xFFFFFFFFu, b0, 1); b0 += __shfl_xor_sync(0xFFFFFFFFu, b0, 2);
                b1 += __shfl_xor_sync(0xFFFFFFFFu, b1, 1); b1 += __shfl_xor_sync(0xFFFFFFFFu, b1, 2);
                int h = wcg * 2 + hh;
                if (tig == 0) {
                    if (r0 < V)     { g_el[r0 * HEADS + h] = a0;       g_er[r0 * HEADS + h] = b0; }
                    if (r0 + 8 < V) { g_el[(r0 + 8) * HEADS + h] = a1; g_er[(r0 + 8) * HEADS + h] = b1; }
                }
            }
        }
    } else {
        // residual + bias into out (fp32)
        int cb = (wcg - 2) * 64;
        float2 bv[8];
        #pragma unroll
        for (int nt = 0; nt < 8; nt++)
            bv[nt] = *reinterpret_cast<const float2*>(bias + cb + nt * 8 + 2 * tig);
        #pragma unroll
        for (int mt = 0; mt < 2; mt++) {
            int r0 = v0 + mbase + mt * 16 + gid;
            #pragma unroll
            for (int nt = 0; nt < 8; nt++) {
                int col = cb + nt * 8 + 2 * tig;
                if (r0 < V)
                    *reinterpret_cast<float2*>(out + (size_t)r0 * HF + col)
                        = make_float2(acc[mt][nt][0] + bv[nt].x, acc[mt][nt][1] + bv[nt].y);
                if (r0 + 8 < V)
                    *reinterpret_cast<float2*>(out + (size_t)(r0 + 8) * HF + col)
                        = make_float2(acc[mt][nt][2] + bv[nt].x, acc[mt][nt][3] + bv[nt].y);
            }
        }
    }
}

// ---------------- edge logits + exp (fp16 out, no atomics) ---------------
__global__ void k_edge(const float* __restrict__ ef, const int* __restrict__ src,
                       const int* __restrict__ dst, int E)
{
    __shared__ float swer[EDGE_IN * HEADS];
    if (threadIdx.x < EDGE_IN * HEADS) swer[threadIdx.x] = g_wer[threadIdx.x];
    __syncthreads();

    int i = blockIdx.x * blockDim.x + threadIdx.x;
    if (i >= E) return;

    float efv[16];
    #pragma unroll
    for (int q = 0; q < 4; q++) {
        float4 e4 = __ldg(reinterpret_cast<const float4*>(ef + (size_t)i * EDGE_IN + q * 4));
        efv[q * 4 + 0] = e4.x; efv[q * 4 + 1] = e4.y; efv[q * 4 + 2] = e4.z; efv[q * 4 + 3] = e4.w;
    }
    float ee0 = 0.f, ee1 = 0.f, ee2 = 0.f, ee3 = 0.f;
    #pragma unroll
    for (int j = 0; j < EDGE_IN; j++) {
        float e = efv[j];
        ee0 += e * swer[j * 4 + 0];
        ee1 += e * swer[j * 4 + 1];
        ee2 += e * swer[j * 4 + 2];
        ee3 += e * swer[j * 4 + 3];
    }

    int s = src[i], d = dst[i];
    float4 el4 = *reinterpret_cast<const float4*>(&g_el[s * HEADS]);
    float4 er4 = *reinterpret_cast<const float4*>(&g_er[d * HEADS]);

    float t0 = el4.x + er4.x + ee0;
    float t1 = el4.y + er4.y + ee1;
    float t2 = el4.z + er4.z + ee2;
    float t3 = el4.w + er4.w + ee3;
    t0 = (t0 >= 0.f) ? t0 : NEG_SLOPE * t0;
    t1 = (t1 >= 0.f) ? t1 : NEG_SLOPE * t1;
    t2 = (t2 >= 0.f) ? t2 : NEG_SLOPE * t2;
    t3 = (t3 >= 0.f) ? t3 : NEG_SLOPE * t3;
    // softmax is shift-invariant; logits are O(1) -> no max pass; the
    // denominator is accumulated inside k_agg (distributive) -> no atomics.
    __half2 h01 = __floats2half2_rn(__expf(t0), __expf(t1));
    __half2 h23 = __floats2half2_rn(__expf(t2), __expf(t3));
    uint2 pk;
    pk.x = *reinterpret_cast<unsigned*>(&h01);
    pk.y = *reinterpret_cast<unsigned*>(&h23);
    *reinterpret_cast<uint2*>(g_exh + (size_t)i * HEADS) = pk;
}

// ---------------- aggregation: one warp per dst ----------------
__global__ void __launch_bounds__(256) k_agg(const int* __restrict__ src,
                                             float* __restrict__ out, int V)
{
    int gw = (blockIdx.x * 256 + threadIdx.x) >> 5;
    int lane = threadIdx.x & 31;
    if (gw >= V) return;
    int v = gw;
    int beg = g_rowptr[v], end = g_rowptr[v + 1];
    if (end <= beg) return;   // out already holds residual + bias

    int h = lane >> 3;
    float4 acc = make_float4(0.f, 0.f, 0.f, 0.f);
    float sacc = 0.0f;

    for (int base = beg; base < end; base += 32) {
        int n = end - base; if (n > 32) n = 32;
        int eid = 0, sv = 0;
        uint2 exu = make_uint2(0, 0);
        if (lane < n) {
            eid = g_csr[base + lane];
            sv  = __ldg(src + eid);
            exu = *reinterpret_cast<const uint2*>(g_exh + (size_t)eid * HEADS);
        }
        #pragma unroll 4
        for (int e = 0; e < n; e++) {
            int sve = __shfl_sync(0xFFFFFFFFu, sv, e);
            unsigned w0 = __shfl_sync(0xFFFFFFFFu, exu.x, e);
            unsigned w1 = __shfl_sync(0xFFFFFFFFu, exu.y, e);
            unsigned wh = (h < 2) ? w0 : w1;
            __half2 hp = *reinterpret_cast<__half2*>(&wh);
            float a = (h & 1) ? __high2float(hp) : __low2float(hp);
            uint2 u = __ldg(reinterpret_cast<const uint2*>(g_fth + (size_t)sve * HF + lane * 4));
            float2 f01 = __half22float2(*reinterpret_cast<__half2*>(&u.x));
            float2 f23 = __half22float2(*reinterpret_cast<__half2*>(&u.y));
            acc.x += a * f01.x; acc.y += a * f01.y;
            acc.z += a * f23.x; acc.w += a * f23.y;
            sacc += a;
        }
    }

    float inv = 1.0f / sacc;
    float4* op = reinterpret_cast<float4*>(out + (size_t)v * HF + lane * 4);
    float4 o = *op;
    o.x += acc.x * inv; o.y += acc.y * inv; o.z += acc.z * inv; o.w += acc.w * inv;
    *op = o;
}

// ---------------- launch with forked capture streams ----------------
static cudaStream_t g_s2 = nullptr;
static cudaEvent_t g_evFork = nullptr, g_evJoin = nullptr;

extern "C" void kernel_launch(void* const* d_in, const int* in_sizes, int n_in,
                              void* d_out, int out_size)
{
    const float* nf   = (const float*)d_in[0];
    const float* ef   = (const float*)d_in[1];
    const int*   src  = (const int*)d_in[2];
    const int*   dst  = (const int*)d_in[3];
    const float* Wn   = (const float*)d_in[4];
    const float* We   = (const float*)d_in[5];
    const float* al   = (const float*)d_in[6];
    const float* ar   = (const float*)d_in[7];
    const float* ae   = (const float*)d_in[8];
    const float* Wr   = (const float*)d_in[9];
    const float* bias = (const float*)d_in[10];
    float* out = (float*)d_out;

    int V = in_sizes[0] / NODE_IN;
    int E = in_sizes[2];
    if (V > MAXV) V = MAXV;
    if (E > MAXE) E = MAXE;

    if (!g_s2) {
        cudaStreamCreateWithFlags(&g_s2, cudaStreamNonBlocking);
        cudaEventCreateWithFlags(&g_evFork, cudaEventDisableTiming);
        cudaEventCreateWithFlags(&g_evJoin, cudaEventDisableTiming);
    }

    const int smemProj = PROJ_ROWS * XS_LD * sizeof(float);   // ~33.8 KB
    int nch = (V + 1023) / 1024;

    cudaEventRecord(g_evFork, 0);
    cudaStreamWaitEvent(g_s2, g_evFork, 0);

    // submission order: #4 = k_edge (profiled slot)
    k_fold<<<(NODE_IN * HF / 2 + 255) / 256, 256>>>(We, ae, Wn, Wr);  // #1 main
    k_zero<<<(V + 255) / 256, 256, 0, g_s2>>>(V);                     // #2 side
    k_nodeproj<<<(V + PROJ_ROWS - 1) / PROJ_ROWS, 256, smemProj>>>(nf, bias, al, ar, out, V);  // #3 main
    k_edge<<<(E + 255) / 256, 256>>>(ef, src, dst, E);                // #4 main (profiled)
    k_hist<<<(E + 255) / 256, 256, 0, g_s2>>>(dst, E);                // #5 side
    k_scan1<<<nch, 1024, 0, g_s2>>>(V);                               // #6 side
    k_scan3<<<nch, 1024, 0, g_s2>>>(V);                               // #7 side
    k_fill<<<(E + 255) / 256, 256, 0, g_s2>>>(dst, E);                // #8 side
    cudaEventRecord(g_evJoin, g_s2);

    cudaStreamWaitEvent(0, g_evJoin, 0);
    k_agg<<<(V * 32 + 255) / 256, 256>>>(src, out, V);                // #9 main
}

// round 11
// speedup vs baseline: 2.0189x; 1.0065x over previous
#include <cuda_runtime.h>
#include <cuda_fp16.h>
#include <cstdint>

#define MAXV 50000
#define MAXE 800000
#define NODE_IN 128
#define EDGE_IN 16
#define HF 128
#define HEADS 4
#define OUTF 32
#define NEG_SLOPE 0.2f
#define PROJ_ROWS 64
#define XS_LD 132   // padded smem stride (floats) -> conflict-free A frags

// ---------------- device scratch ----------------
__device__ __half g_fth[MAXV * HF];     // projected node feats (fp16)
__device__ __half g_exh[MAXE * HEADS];  // exp(logit) per edge (fp16 x4)
__device__ float g_ee[MAXE * HEADS];    // edge-feature logits (fp32)
__device__ float g_el[MAXV * HEADS];
__device__ float g_er[MAXV * HEADS];
__device__ int   g_deg[MAXV];
__device__ int   g_incl[MAXV];
__device__ int   g_bsum[64];
__device__ int   g_rowptr[MAXV + 1];
__device__ int   g_cursor[MAXV];
__device__ int   g_csr[MAXE];
__device__ float g_wer[EDGE_IN * HEADS];
// pair-packed tf32 weights: index ((ks*HF + col)*4 + tig) -> (k=ks*8+tig, k+4)
__device__ uint2 g_wnr2[(NODE_IN / 8) * HF * 4];
__device__ uint2 g_wrr2[(NODE_IN / 8) * HF * 4];

__device__ __forceinline__ unsigned tf32r(float x) {
    unsigned u;
    asm("cvt.rna.tf32.f32 %0, %1;" : "=r"(u) : "f"(x));
    return u;
}

__device__ __forceinline__ void mma_tf32(float* d, const unsigned* a, const unsigned* b) {
    asm volatile(
        "mma.sync.aligned.m16n8k8.row.col.f32.tf32.tf32.f32 "
        "{%0,%1,%2,%3}, {%4,%5,%6,%7}, {%8,%9}, {%0,%1,%2,%3};"
        : "+f"(d[0]), "+f"(d[1]), "+f"(d[2]), "+f"(d[3])
        : "r"(a[0]), "r"(a[1]), "r"(a[2]), "r"(a[3]), "r"(b[0]), "r"(b[1]));
}

// ---------------- CSR-build kernels (side stream s2) ----------------
__global__ void k_zero(int V) {
    int i = blockIdx.x * blockDim.x + threadIdx.x;
    if (i < V) g_deg[i] = 0;
}

__global__ void k_hist(const int* __restrict__ dst, int E) {
    int i = blockIdx.x * blockDim.x + threadIdx.x;
    if (i < E) atomicAdd(&g_deg[dst[i]], 1);
}

__global__ void k_scan1(int V) {
    __shared__ int wsum[32];
    int b = blockIdx.x, t = threadIdx.x;
    int i = b * 1024 + t;
    int val = (i < V) ? g_deg[i] : 0;
    int lane = t & 31, wid = t >> 5;
    int x = val;
    #pragma unroll
    for (int o = 1; o < 32; o <<= 1) {
        int y = __shfl_up_sync(0xFFFFFFFFu, x, o);
        if (lane >= o) x += y;
    }
    if (lane == 31) wsum[wid] = x;
    __syncthreads();
    if (wid == 0) {
        int s = wsum[lane];
        #pragma unroll
        for (int o = 1; o < 32; o <<= 1) {
            int y = __shfl_up_sync(0xFFFFFFFFu, s, o);
            if (lane >= o) s += y;
        }
        wsum[lane] = s;
    }
    __syncthreads();
    int incl = x + (wid > 0 ? wsum[wid - 1] : 0);
    if (i < V) g_incl[i] = incl;
    if (t == 1023) g_bsum[b] = incl;
}

__global__ void k_scan3(int V) {
    __shared__ int soff;
    int b = blockIdx.x, t = threadIdx.x;
    if (t < 32) {
        int s = 0;
        for (int j = t; j < b; j += 32) s += g_bsum[j];
        #pragma unroll
        for (int o = 16; o > 0; o >>= 1) s += __shfl_xor_sync(0xFFFFFFFFu, s, o);
        if (t == 0) soff = s;
    }
    __syncthreads();
    int i = b * 1024 + t;
    if (i < V) {
        int incl = g_incl[i] + soff;
        g_rowptr[i + 1] = incl;
        g_cursor[i] = incl - g_deg[i];
        if (i == 0) g_rowptr[0] = 0;
    }
}

__global__ void k_fill(const int* __restrict__ dst, int E) {
    int i = blockIdx.x * blockDim.x + threadIdx.x;
    if (i < E) {
        int pos = atomicAdd(&g_cursor[dst[i]], 1);
        g_csr[pos] = i;
    }
}

// ---------------- fold + tf32 weight rounding into pair-packed layout ----
__global__ void k_fold(const float* __restrict__ We, const float* __restrict__ ae,
                       const float* __restrict__ Wn, const float* __restrict__ Wr) {
    int i = blockIdx.x * blockDim.x + threadIdx.x;
    int NP = (NODE_IN / 8) * HF * 4;     // 8192
    if (i < NP) {
        int ks  = i >> 9;                // /(HF*4)
        int col = (i >> 2) & (HF - 1);
        int tig = i & 3;
        int k0 = ks * 8 + tig;
        g_wnr2[i] = make_uint2(tf32r(Wn[(size_t)k0 * HF + col]),
                               tf32r(Wn[(size_t)(k0 + 4) * HF + col]));
        g_wrr2[i] = make_uint2(tf32r(Wr[(size_t)k0 * HF + col]),
                               tf32r(Wr[(size_t)(k0 + 4) * HF + col]));
    }
    if (blockIdx.x == 0 && threadIdx.x < EDGE_IN * HEADS) {
        int t = threadIdx.x;
        int j = t >> 2, h = t & 3;
        float s = 0.0f;
        #pragma unroll
        for (int f = 0; f < OUTF; f++)
            s += We[j * HF + h * OUTF + f] * ae[h * OUTF + f];
        g_wer[j * HEADS + h] = s;
    }
}

// ---------------- edge-feature logits (stream s3, overlaps nodeproj) -----
// Coalesced smem staging: block loads 256 edges' features (16 KB) with
// contiguous float4s, then threads read their edge's row from padded smem.
__global__ void __launch_bounds__(256) k_ee(const float* __restrict__ ef, int E)
{
    __shared__ float swer[EDGE_IN * HEADS];
    __shared__ float sef[256 * 17];     // stride-17 pad -> conflict-free reads

    if (threadIdx.x < EDGE_IN * HEADS) swer[threadIdx.x] = g_wer[threadIdx.x];

    int base = blockIdx.x * 256;
    int nEdge = E - base; if (nEdge > 256) nEdge = 256;

    int nF4 = nEdge * 4;                // 16 floats per edge / 4
    const float4* efp = reinterpret_cast<const float4*>(ef) + (size_t)base * 4;
    for (int i = threadIdx.x; i < nF4; i += 256) {
        float4 f = __ldg(efp + i);
        int e = i >> 2, j0 = (i & 3) * 4;
        float* p = &sef[e * 17 + j0];
        p[0] = f.x; p[1] = f.y; p[2] = f.z; p[3] = f.w;
    }
    __syncthreads();

    int t = threadIdx.x;
    if (t >= nEdge) return;

    const float* row = &sef[t * 17];
    float ee0 = 0.f, ee1 = 0.f, ee2 = 0.f, ee3 = 0.f;
    #pragma unroll
    for (int j = 0; j < EDGE_IN; j++) {
        float e = row[j];
        ee0 += e * swer[j * 4 + 0];
        ee1 += e * swer[j * 4 + 1];
        ee2 += e * swer[j * 4 + 2];
        ee3 += e * swer[j * 4 + 3];
    }
    *reinterpret_cast<float4*>(&g_ee[(size_t)(base + t) * HEADS]) =
        make_float4(ee0, ee1, ee2, ee3);
}

// ---------------- node projection via TF32 HMMA ----------------
// 256 threads, 64-row tile. Warp grid: 2 row halves x 4 col groups of 64.
__global__ void __launch_bounds__(256, 2) k_nodeproj(
    const float* __restrict__ nf, const float* __restrict__ bias,
    const float* __restrict__ al, const float* __restrict__ ar,
    float* __restrict__ out, int V)
{
    extern __shared__ float xs[];   // [64][XS_LD]
    int v0 = blockIdx.x * PROJ_ROWS;
    int tid = threadIdx.x;

    #pragma unroll
    for (int i = 0; i < 8; i++) {
        int idx = tid + i * 256;
        int r = idx >> 5;
        int c4 = idx & 31;
        int v = v0 + r;
        float4 val = make_float4(0.f, 0.f, 0.f, 0.f);
        if (v < V) val = *reinterpret_cast<const float4*>(nf + (size_t)v * NODE_IN + c4 * 4);
        val.x = __uint_as_float(tf32r(val.x));
        val.y = __uint_as_float(tf32r(val.y));
        val.z = __uint_as_float(tf32r(val.z));
        val.w = __uint_as_float(tf32r(val.w));
        *reinterpret_cast<float4*>(&xs[r * XS_LD + c4 * 4]) = val;
    }
    __syncthreads();

    int lane = tid & 31;
    int warp = tid >> 5;
    int wrow = warp & 1;
    int wcg  = warp >> 1;
    int tig  = lane & 3;
    int gid  = lane >> 2;

    const uint2* B2 = (wcg < 2) ? g_wnr2 : g_wrr2;
    int nb = (wcg & 1) * 64;
    int mbase = wrow * 32;

    float acc[2][8][4];
    #pragma unroll
    for (int mt = 0; mt < 2; mt++)
        #pragma unroll
        for (int nt = 0; nt < 8; nt++)
            #pragma unroll
            for (int q = 0; q < 4; q++) acc[mt][nt][q] = 0.f;

    #pragma unroll 2
    for (int ks = 0; ks < 16; ks++) {
        int kb = ks * 8;
        unsigned a[2][4];
        #pragma unroll
        for (int mt = 0; mt < 2; mt++) {
            int r0 = mbase + mt * 16 + gid;
            a[mt][0] = __float_as_uint(xs[r0 * XS_LD + kb + tig]);
            a[mt][1] = __float_as_uint(xs[(r0 + 8) * XS_LD + kb + tig]);
            a[mt][2] = __float_as_uint(xs[r0 * XS_LD + kb + tig + 4]);
            a[mt][3] = __float_as_uint(xs[(r0 + 8) * XS_LD + kb + tig + 4]);
        }
        unsigned b[8][2];
        #pragma unroll
        for (int nt = 0; nt < 8; nt++) {
            int col = nb + nt * 8 + gid;
            uint2 bp = __ldg(&B2[(ks * HF + col) * 4 + tig]);
            b[nt][0] = bp.x;
            b[nt][1] = bp.y;
        }
        #pragma unroll
        for (int mt = 0; mt < 2; mt++)
            #pragma unroll
            for (int nt = 0; nt < 8; nt++)
                mma_tf32(acc[mt][nt], a[mt], b[nt]);
    }

    if (wcg < 2) {
        float2 alf[8], arf[8];
        #pragma unroll
        for (int nt = 0; nt < 8; nt++) {
            int h = wcg * 2 + (nt >> 2);
            int off = h * OUTF + (nt & 3) * 8 + 2 * tig;
            alf[nt] = *reinterpret_cast<const float2*>(al + off);
            arf[nt] = *reinterpret_cast<const float2*>(ar + off);
        }
        #pragma unroll
        for (int mt = 0; mt < 2; mt++) {
            int r0 = v0 + mbase + mt * 16 + gid;
            float el0[2] = {0.f, 0.f}, el1[2] = {0.f, 0.f};
            float er0[2] = {0.f, 0.f}, er1[2] = {0.f, 0.f};
            #pragma unroll
            for (int nt = 0; nt < 8; nt++) {
                int hh = nt >> 2;
                el0[hh] += acc[mt][nt][0] * alf[nt].x + acc[mt][nt][1] * alf[nt].y;
                el1[hh] += acc[mt][nt][2] * alf[nt].x + acc[mt][nt][3] * alf[nt].y;
                er0[hh] += acc[mt][nt][0] * arf[nt].x + acc[mt][nt][1] * arf[nt].y;
                er1[hh] += acc[mt][nt][2] * arf[nt].x + acc[mt][nt][3] * arf[nt].y;
                int col = wcg * 64 + nt * 8 + 2 * tig;
                if (r0 < V)
                    *reinterpret_cast<__half2*>(g_fth + (size_t)r0 * HF + col)
                        = __floats2half2_rn(acc[mt][nt][0], acc[mt][nt][1]);
                if (r0 + 8 < V)
                    *reinterpret_cast<__half2*>(g_fth + (size_t)(r0 + 8) * HF + col)
                        = __floats2half2_rn(acc[mt][nt][2], acc[mt][nt][3]);
            }
            #pragma unroll
            for (int hh = 0; hh < 2; hh++) {
                float a0 = el0[hh], a1 = el1[hh], b0 = er0[hh], b1 = er1[hh];
                a0 += __shfl_xor_sync(0xFFFFFFFFu, a0, 1); a0 += __shfl_xor_sync(0xFFFFFFFFu, a0, 2);
                a1 += __shfl_xor_sync(0xFFFFFFFFu, a1, 1); a1 += __shfl_xor_sync(0xFFFFFFFFu, a1, 2);
                b0 += __shfl_xor_sync(0xFFFFFFFFu, b0, 1); b0 += __shfl_xor_sync(0xFFFFFFFFu, b0, 2);
                b1 += __shfl_xor_sync(0xFFFFFFFFu, b1, 1); b1 += __shfl_xor_sync(0xFFFFFFFFu, b1, 2);
                int h = wcg * 2 + hh;
                if (tig == 0) {
                    if (r0 < V)     { g_el[r0 * HEADS + h] = a0;       g_er[r0 * HEADS + h] = b0; }
                    if (r0 + 8 < V) { g_el[(r0 + 8) * HEADS + h] = a1; g_er[(r0 + 8) * HEADS + h] = b1; }
                }
            }
        }
    } else {
        int cb = (wcg - 2) * 64;
        float2 bv[8];
        #pragma unroll
        for (int nt = 0; nt < 8; nt++)
            bv[nt] = *reinterpret_cast<const float2*>(bias + cb + nt * 8 + 2 * tig);
        #pragma unroll
        for (int mt = 0; mt < 2; mt++) {
            int r0 = v0 + mbase + mt * 16 + gid;
            #pragma unroll
            for (int nt = 0; nt < 8; nt++) {
                int col = cb + nt * 8 + 2 * tig;
                if (r0 < V)
                    *reinterpret_cast<float2*>(out + (size_t)r0 * HF + col)
                        = make_float2(acc[mt][nt][0] + bv[nt].x, acc[mt][nt][1] + bv[nt].y);
                if (r0 + 8 < V)
                    *reinterpret_cast<float2*>(out + (size_t)(r0 + 8) * HF + col)
                        = make_float2(acc[mt][nt][2] + bv[nt].x, acc[mt][nt][3] + bv[nt].y);
            }
        }
    }
}

// ---------------- edge logits part 2: gather + exp (light) ---------------
__global__ void __launch_bounds__(256) k_edge2(const int* __restrict__ src,
                                               const int* __restrict__ dst, int E)
{
    int i = blockIdx.x * blockDim.x + threadIdx.x;
    if (i >= E) return;

    float4 ee4 = *reinterpret_cast<const float4*>(&g_ee[(size_t)i * HEADS]);
    int s = src[i], d = dst[i];
    float4 el4 = *reinterpret_cast<const float4*>(&g_el[s * HEADS]);
    float4 er4 = *reinterpret_cast<const float4*>(&g_er[d * HEADS]);

    float t0 = el4.x + er4.x + ee4.x;
    float t1 = el4.y + er4.y + ee4.y;
    float t2 = el4.z + er4.z + ee4.z;
    float t3 = el4.w + er4.w + ee4.w;
    t0 = (t0 >= 0.f) ? t0 : NEG_SLOPE * t0;
    t1 = (t1 >= 0.f) ? t1 : NEG_SLOPE * t1;
    t2 = (t2 >= 0.f) ? t2 : NEG_SLOPE * t2;
    t3 = (t3 >= 0.f) ? t3 : NEG_SLOPE * t3;
    // softmax is shift-invariant; logits are O(1) -> no max pass; the
    // denominator is accumulated inside k_agg (distributive) -> no atomics.
    __half2 h01 = __floats2half2_rn(__expf(t0), __expf(t1));
    __half2 h23 = __floats2half2_rn(__expf(t2), __expf(t3));
    uint2 pk;
    pk.x = *reinterpret_cast<unsigned*>(&h01);
    pk.y = *reinterpret_cast<unsigned*>(&h23);
    *reinterpret_cast<uint2*>(g_exh + (size_t)i * HEADS) = pk;
}

// ---------------- aggregation: one warp per dst ----------------
__global__ void __launch_bounds__(256) k_agg(const int* __restrict__ src,
                                             float* __restrict__ out, int V)
{
    int gw = (blockIdx.x * 256 + threadIdx.x) >> 5;
    int lane = threadIdx.x & 31;
    if (gw >= V) return;
    int v = gw;
    int beg = g_rowptr[v], end = g_rowptr[v + 1];
    if (end <= beg) return;   // out already holds residual + bias

    int h = lane >> 3;
    float4 acc = make_float4(0.f, 0.f, 0.f, 0.f);
    float sacc = 0.0f;

    for (int base = beg; base < end; base += 32) {
        int n = end - base; if (n > 32) n = 32;
        int eid = 0, sv = 0;
        uint2 exu = make_uint2(0, 0);
        if (lane < n) {
            eid = g_csr[base + lane];
            sv  = __ldg(src + eid);
            exu = *reinterpret_cast<const uint2*>(g_exh + (size_t)eid * HEADS);
        }
        #pragma unroll 4
        for (int e = 0; e < n; e++) {
            int sve = __shfl_sync(0xFFFFFFFFu, sv, e);
            unsigned w0 = __shfl_sync(0xFFFFFFFFu, exu.x, e);
            unsigned w1 = __shfl_sync(0xFFFFFFFFu, exu.y, e);
            unsigned wh = (h < 2) ? w0 : w1;
            __half2 hp = *reinterpret_cast<__half2*>(&wh);
            float a = (h & 1) ? __high2float(hp) : __low2float(hp);
            uint2 u = __ldg(reinterpret_cast<const uint2*>(g_fth + (size_t)sve * HF + lane * 4));
            float2 f01 = __half22float2(*reinterpret_cast<__half2*>(&u.x));
            float2 f23 = __half22float2(*reinterpret_cast<__half2*>(&u.y));
            acc.x += a * f01.x; acc.y += a * f01.y;
            acc.z += a * f23.x; acc.w += a * f23.y;
            sacc += a;
        }
    }

    float inv = 1.0f / sacc;
    float4* op = reinterpret_cast<float4*>(out + (size_t)v * HF + lane * 4);
    float4 o = *op;
    o.x += acc.x * inv; o.y += acc.y * inv; o.z += acc.z * inv; o.w += acc.w * inv;
    *op = o;
}

// ---------------- launch: three-stream forked capture ----------------
static cudaStream_t g_s2 = nullptr, g_s3 = nullptr;
static cudaEvent_t g_evFork = nullptr, g_evJoin = nullptr, g_evFold = nullptr, g_evEE = nullptr;

extern "C" void kernel_launch(void* const* d_in, const int* in_sizes, int n_in,
                              void* d_out, int out_size)
{
    const float* nf   = (const float*)d_in[0];
    const float* ef   = (const float*)d_in[1];
    const int*   src  = (const int*)d_in[2];
    const int*   dst  = (const int*)d_in[3];
    const float* Wn   = (const float*)d_in[4];
    const float* We   = (const float*)d_in[5];
    const float* al   = (const float*)d_in[6];
    const float* ar   = (const float*)d_in[7];
    const float* ae   = (const float*)d_in[8];
    const float* Wr   = (const float*)d_in[9];
    const float* bias = (const float*)d_in[10];
    float* out = (float*)d_out;

    int V = in_sizes[0] / NODE_IN;
    int E = in_sizes[2];
    if (V > MAXV) V = MAXV;
    if (E > MAXE) E = MAXE;

    if (!g_s2) {
        cudaStreamCreateWithFlags(&g_s2, cudaStreamNonBlocking);
        cudaStreamCreateWithFlags(&g_s3, cudaStreamNonBlocking);
        cudaEventCreateWithFlags(&g_evFork, cudaEventDisableTiming);
        cudaEventCreateWithFlags(&g_evJoin, cudaEventDisableTiming);
        cudaEventCreateWithFlags(&g_evFold, cudaEventDisableTiming);
        cudaEventCreateWithFlags(&g_evEE, cudaEventDisableTiming);
    }

    const int smemProj = PROJ_ROWS * XS_LD * sizeof(float);   // ~33.8 KB
    int nch = (V + 1023) / 1024;

    cudaEventRecord(g_evFork, 0);
    cudaStreamWaitEvent(g_s2, g_evFork, 0);
    cudaStreamWaitEvent(g_s3, g_evFork, 0);

    k_fold<<<(NODE_IN * HF / 2 + 255) / 256, 256>>>(We, ae, Wn, Wr);  // main
    cudaEventRecord(g_evFold, 0);

    // s3: ef-streaming edge GEMM, overlapped under nodeproj
    cudaStreamWaitEvent(g_s3, g_evFold, 0);
    k_ee<<<(E + 255) / 256, 256, 0, g_s3>>>(ef, E);
    cudaEventRecord(g_evEE, g_s3);

    // s2: CSR build
    k_zero<<<(V + 255) / 256, 256, 0, g_s2>>>(V);
    k_hist<<<(E + 255) / 256, 256, 0, g_s2>>>(dst, E);
    k_scan1<<<nch, 1024, 0, g_s2>>>(V);
    k_scan3<<<nch, 1024, 0, g_s2>>>(V);
    k_fill<<<(E + 255) / 256, 256, 0, g_s2>>>(dst, E);
    cudaEventRecord(g_evJoin, g_s2);

    // main chain
    k_nodeproj<<<(V + PROJ_ROWS - 1) / PROJ_ROWS, 256, smemProj>>>(nf, bias, al, ar, out, V);
    cudaStreamWaitEvent(0, g_evEE, 0);
    k_edge2<<<(E + 255) / 256, 256>>>(src, dst, E);
    cudaStreamWaitEvent(0, g_evJoin, 0);
    k_agg<<<(V * 32 + 255) / 256, 256>>>(src, out, V);
}

// round 12
// speedup vs baseline: 2.0564x; 1.0186x over previous
#include <cuda_runtime.h>
#include <cuda_fp16.h>
#include <cstdint>

#define MAXV 50000
#define MAXE 800000
#define NODE_IN 128
#define EDGE_IN 16
#define HF 128
#define HEADS 4
#define OUTF 32
#define NEG_SLOPE 0.2f
#define PROJ_ROWS 64
#define XS_LD 132   // padded smem stride (floats) -> conflict-free A frags

// ---------------- device scratch ----------------
__device__ __half g_fth[MAXV * HF];     // projected node feats (fp16)
__device__ float g_ee[MAXE * HEADS];    // edge-feature logits (fp32)
__device__ float g_el[MAXV * HEADS];
__device__ float g_er[MAXV * HEADS];
__device__ int   g_deg[MAXV];
__device__ int   g_incl[MAXV];
__device__ int   g_bsum[64];
__device__ int   g_rowptr[MAXV + 1];
__device__ int   g_cursor[MAXV];
__device__ int   g_csr[MAXE];
__device__ float g_wer[EDGE_IN * HEADS];
// pair-packed tf32 weights: index ((ks*HF + col)*4 + tig) -> (k=ks*8+tig, k+4)
__device__ uint2 g_wnr2[(NODE_IN / 8) * HF * 4];
__device__ uint2 g_wrr2[(NODE_IN / 8) * HF * 4];

__device__ __forceinline__ unsigned tf32r(float x) {
    unsigned u;
    asm("cvt.rna.tf32.f32 %0, %1;" : "=r"(u) : "f"(x));
    return u;
}

__device__ __forceinline__ void mma_tf32(float* d, const unsigned* a, const unsigned* b) {
    asm volatile(
        "mma.sync.aligned.m16n8k8.row.col.f32.tf32.tf32.f32 "
        "{%0,%1,%2,%3}, {%4,%5,%6,%7}, {%8,%9}, {%0,%1,%2,%3};"
        : "+f"(d[0]), "+f"(d[1]), "+f"(d[2]), "+f"(d[3])
        : "r"(a[0]), "r"(a[1]), "r"(a[2]), "r"(a[3]), "r"(b[0]), "r"(b[1]));
}

// ---------------- CSR-build kernels (side stream s2) ----------------
__global__ void k_zero(int V) {
    int i = blockIdx.x * blockDim.x + threadIdx.x;
    if (i < V) g_deg[i] = 0;
}

// 4 edges per thread for MLP
__global__ void k_hist(const int* __restrict__ dst, int E) {
    int i = blockIdx.x * blockDim.x + threadIdx.x;
    int b = i * 4;
    if (b + 3 < E) {
        int4 d4 = __ldg(reinterpret_cast<const int4*>(dst) + i);
        atomicAdd(&g_deg[d4.x], 1);
        atomicAdd(&g_deg[d4.y], 1);
        atomicAdd(&g_deg[d4.z], 1);
        atomicAdd(&g_deg[d4.w], 1);
    } else {
        for (int j = b; j < E; j++) atomicAdd(&g_deg[dst[j]], 1);
    }
}

__global__ void k_scan1(int V) {
    __shared__ int wsum[32];
    int b = blockIdx.x, t = threadIdx.x;
    int i = b * 1024 + t;
    int val = (i < V) ? g_deg[i] : 0;
    int lane = t & 31, wid = t >> 5;
    int x = val;
    #pragma unroll
    for (int o = 1; o < 32; o <<= 1) {
        int y = __shfl_up_sync(0xFFFFFFFFu, x, o);
        if (lane >= o) x += y;
    }
    if (lane == 31) wsum[wid] = x;
    __syncthreads();
    if (wid == 0) {
        int s = wsum[lane];
        #pragma unroll
        for (int o = 1; o < 32; o <<= 1) {
            int y = __shfl_up_sync(0xFFFFFFFFu, s, o);
            if (lane >= o) s += y;
        }
        wsum[lane] = s;
    }
    __syncthreads();
    int incl = x + (wid > 0 ? wsum[wid - 1] : 0);
    if (i < V) g_incl[i] = incl;
    if (t == 1023) g_bsum[b] = incl;
}

__global__ void k_scan3(int V) {
    __shared__ int soff;
    int b = blockIdx.x, t = threadIdx.x;
    if (t < 32) {
        int s = 0;
        for (int j = t; j < b; j += 32) s += g_bsum[j];
        #pragma unroll
        for (int o = 16; o > 0; o >>= 1) s += __shfl_xor_sync(0xFFFFFFFFu, s, o);
        if (t == 0) soff = s;
    }
    __syncthreads();
    int i = b * 1024 + t;
    if (i < V) {
        int incl = g_incl[i] + soff;
        g_rowptr[i + 1] = incl;
        g_cursor[i] = incl - g_deg[i];
        if (i == 0) g_rowptr[0] = 0;
    }
}

// 4 edges per thread for MLP
__global__ void k_fill(const int* __restrict__ dst, int E) {
    int i = blockIdx.x * blockDim.x + threadIdx.x;
    int b = i * 4;
    if (b + 3 < E) {
        int4 d4 = __ldg(reinterpret_cast<const int4*>(dst) + i);
        int p0 = atomicAdd(&g_cursor[d4.x], 1);
        int p1 = atomicAdd(&g_cursor[d4.y], 1);
        int p2 = atomicAdd(&g_cursor[d4.z], 1);
        int p3 = atomicAdd(&g_cursor[d4.w], 1);
        g_csr[p0] = b;
        g_csr[p1] = b + 1;
        g_csr[p2] = b + 2;
        g_csr[p3] = b + 3;
    } else {
        for (int j = b; j < E; j++) {
            int pos = atomicAdd(&g_cursor[dst[j]], 1);
            g_csr[pos] = j;
        }
    }
}

// ---------------- fold + tf32 weight rounding into pair-packed layout ----
__global__ void k_fold(const float* __restrict__ We, const float* __restrict__ ae,
                       const float* __restrict__ Wn, const float* __restrict__ Wr) {
    int i = blockIdx.x * blockDim.x + threadIdx.x;
    int NP = (NODE_IN / 8) * HF * 4;     // 8192
    if (i < NP) {
        int ks  = i >> 9;                // /(HF*4)
        int col = (i >> 2) & (HF - 1);
        int tig = i & 3;
        int k0 = ks * 8 + tig;
        g_wnr2[i] = make_uint2(tf32r(Wn[(size_t)k0 * HF + col]),
                               tf32r(Wn[(size_t)(k0 + 4) * HF + col]));
        g_wrr2[i] = make_uint2(tf32r(Wr[(size_t)k0 * HF + col]),
                               tf32r(Wr[(size_t)(k0 + 4) * HF + col]));
    }
    if (blockIdx.x == 0 && threadIdx.x < EDGE_IN * HEADS) {
        int t = threadIdx.x;
        int j = t >> 2, h = t & 3;
        float s = 0.0f;
        #pragma unroll
        for (int f = 0; f < OUTF; f++)
            s += We[j * HF + h * OUTF + f] * ae[h * OUTF + f];
        g_wer[j * HEADS + h] = s;
    }
}

// ---------------- edge-feature logits (stream s3, overlaps nodeproj) -----
__global__ void __launch_bounds__(256) k_ee(const float* __restrict__ ef, int E)
{
    __shared__ float swer[EDGE_IN * HEADS];
    __shared__ float sef[256 * 17];     // stride-17 pad -> conflict-free reads

    if (threadIdx.x < EDGE_IN * HEADS) swer[threadIdx.x] = g_wer[threadIdx.x];

    int base = blockIdx.x * 256;
    int nEdge = E - base; if (nEdge > 256) nEdge = 256;

    int nF4 = nEdge * 4;                // 16 floats per edge / 4
    const float4* efp = reinterpret_cast<const float4*>(ef) + (size_t)base * 4;
    for (int i = threadIdx.x; i < nF4; i += 256) {
        float4 f = __ldg(efp + i);
        int e = i >> 2, j0 = (i & 3) * 4;
        float* p = &sef[e * 17 + j0];
        p[0] = f.x; p[1] = f.y; p[2] = f.z; p[3] = f.w;
    }
    __syncthreads();

    int t = threadIdx.x;
    if (t >= nEdge) return;

    const float* row = &sef[t * 17];
    float ee0 = 0.f, ee1 = 0.f, ee2 = 0.f, ee3 = 0.f;
    #pragma unroll
    for (int j = 0; j < EDGE_IN; j++) {
        float e = row[j];
        ee0 += e * swer[j * 4 + 0];
        ee1 += e * swer[j * 4 + 1];
        ee2 += e * swer[j * 4 + 2];
        ee3 += e * swer[j * 4 + 3];
    }
    *reinterpret_cast<float4*>(&g_ee[(size_t)(base + t) * HEADS]) =
        make_float4(ee0, ee1, ee2, ee3);
}

// ---------------- node projection via TF32 HMMA ----------------
__global__ void __launch_bounds__(256, 2) k_nodeproj(
    const float* __restrict__ nf, const float* __restrict__ bias,
    const float* __restrict__ al, const float* __restrict__ ar,
    float* __restrict__ out, int V)
{
    extern __shared__ float xs[];   // [64][XS_LD]
    int v0 = blockIdx.x * PROJ_ROWS;
    int tid = threadIdx.x;

    #pragma unroll
    for (int i = 0; i < 8; i++) {
        int idx = tid + i * 256;
        int r = idx >> 5;
        int c4 = idx & 31;
        int v = v0 + r;
        float4 val = make_float4(0.f, 0.f, 0.f, 0.f);
        if (v < V) val = *reinterpret_cast<const float4*>(nf + (size_t)v * NODE_IN + c4 * 4);
        val.x = __uint_as_float(tf32r(val.x));
        val.y = __uint_as_float(tf32r(val.y));
        val.z = __uint_as_float(tf32r(val.z));
        val.w = __uint_as_float(tf32r(val.w));
        *reinterpret_cast<float4*>(&xs[r * XS_LD + c4 * 4]) = val;
    }
    __syncthreads();

    int lane = tid & 31;
    int warp = tid >> 5;
    int wrow = warp & 1;
    int wcg  = warp >> 1;
    int tig  = lane & 3;
    int gid  = lane >> 2;

    const uint2* B2 = (wcg < 2) ? g_wnr2 : g_wrr2;
    int nb = (wcg & 1) * 64;
    int mbase = wrow * 32;

    float acc[2][8][4];
    #pragma unroll
    for (int mt = 0; mt < 2; mt++)
        #pragma unroll
        for (int nt = 0; nt < 8; nt++)
            #pragma unroll
            for (int q = 0; q < 4; q++) acc[mt][nt][q] = 0.f;

    #pragma unroll 2
    for (int ks = 0; ks < 16; ks++) {
        int kb = ks * 8;
        unsigned a[2][4];
        #pragma unroll
        for (int mt = 0; mt < 2; mt++) {
            int r0 = mbase + mt * 16 + gid;
            a[mt][0] = __float_as_uint(xs[r0 * XS_LD + kb + tig]);
            a[mt][1] = __float_as_uint(xs[(r0 + 8) * XS_LD + kb + tig]);
            a[mt][2] = __float_as_uint(xs[r0 * XS_LD + kb + tig + 4]);
            a[mt][3] = __float_as_uint(xs[(r0 + 8) * XS_LD + kb + tig + 4]);
        }
        unsigned b[8][2];
        #pragma unroll
        for (int nt = 0; nt < 8; nt++) {
            int col = nb + nt * 8 + gid;
            uint2 bp = __ldg(&B2[(ks * HF + col) * 4 + tig]);
            b[nt][0] = bp.x;
            b[nt][1] = bp.y;
        }
        #pragma unroll
        for (int mt = 0; mt < 2; mt++)
            #pragma unroll
            for (int nt = 0; nt < 8; nt++)
                mma_tf32(acc[mt][nt], a[mt], b[nt]);
    }

    if (wcg < 2) {
        float2 alf[8], arf[8];
        #pragma unroll
        for (int nt = 0; nt < 8; nt++) {
            int h = wcg * 2 + (nt >> 2);
            int off = h * OUTF + (nt & 3) * 8 + 2 * tig;
            alf[nt] = *reinterpret_cast<const float2*>(al + off);
            arf[nt] = *reinterpret_cast<const float2*>(ar + off);
        }
        #pragma unroll
        for (int mt = 0; mt < 2; mt++) {
            int r0 = v0 + mbase + mt * 16 + gid;
            float el0[2] = {0.f, 0.f}, el1[2] = {0.f, 0.f};
            float er0[2] = {0.f, 0.f}, er1[2] = {0.f, 0.f};
            #pragma unroll
            for (int nt = 0; nt < 8; nt++) {
                int hh = nt >> 2;
                el0[hh] += acc[mt][nt][0] * alf[nt].x + acc[mt][nt][1] * alf[nt].y;
                el1[hh] += acc[mt][nt][2] * alf[nt].x + acc[mt][nt][3] * alf[nt].y;
                er0[hh] += acc[mt][nt][0] * arf[nt].x + acc[mt][nt][1] * arf[nt].y;
                er1[hh] += acc[mt][nt][2] * arf[nt].x + acc[mt][nt][3] * arf[nt].y;
                int col = wcg * 64 + nt * 8 + 2 * tig;
                if (r0 < V)
                    *reinterpret_cast<__half2*>(g_fth + (size_t)r0 * HF + col)
                        = __floats2half2_rn(acc[mt][nt][0], acc[mt][nt][1]);
                if (r0 + 8 < V)
                    *reinterpret_cast<__half2*>(g_fth + (size_t)(r0 + 8) * HF + col)
                        = __floats2half2_rn(acc[mt][nt][2], acc[mt][nt][3]);
            }
            #pragma unroll
            for (int hh = 0; hh < 2; hh++) {
                float a0 = el0[hh], a1 = el1[hh], b0 = er0[hh], b1 = er1[hh];
                a0 += __shfl_xor_sync(0xFFFFFFFFu, a0, 1); a0 += __shfl_xor_sync(0xFFFFFFFFu, a0, 2);
                a1 += __shfl_xor_sync(0xFFFFFFFFu, a1, 1); a1 += __shfl_xor_sync(0xFFFFFFFFu, a1, 2);
                b0 += __shfl_xor_sync(0xFFFFFFFFu, b0, 1); b0 += __shfl_xor_sync(0xFFFFFFFFu, b0, 2);
                b1 += __shfl_xor_sync(0xFFFFFFFFu, b1, 1); b1 += __shfl_xor_sync(0xFFFFFFFFu, b1, 2);
                int h = wcg * 2 + hh;
                if (tig == 0) {
                    if (r0 < V)     { g_el[r0 * HEADS + h] = a0;       g_er[r0 * HEADS + h] = b0; }
                    if (r0 + 8 < V) { g_el[(r0 + 8) * HEADS + h] = a1; g_er[(r0 + 8) * HEADS + h] = b1; }
                }
            }
        }
    } else {
        int cb = (wcg - 2) * 64;
        float2 bv[8];
        #pragma unroll
        for (int nt = 0; nt < 8; nt++)
            bv[nt] = *reinterpret_cast<const float2*>(bias + cb + nt * 8 + 2 * tig);
        #pragma unroll
        for (int mt = 0; mt < 2; mt++) {
            int r0 = v0 + mbase + mt * 16 + gid;
            #pragma unroll
            for (int nt = 0; nt < 8; nt++) {
                int col = cb + nt * 8 + 2 * tig;
                if (r0 < V)
                    *reinterpret_cast<float2*>(out + (size_t)r0 * HF + col)
                        = make_float2(acc[mt][nt][0] + bv[nt].x, acc[mt][nt][1] + bv[nt].y);
                if (r0 + 8 < V)
                    *reinterpret_cast<float2*>(out + (size_t)(r0 + 8) * HF + col)
                        = make_float2(acc[mt][nt][2] + bv[nt].x, acc[mt][nt][3] + bv[nt].y);
            }
        }
    }
}

// ---------------- aggregation: one warp per dst, fused exp ----------------
// Staging lanes compute logit+exp inline (ee[eid] + el[src] + er[v]),
// pack to half2x2, then broadcast via 2 shfls in the inner loop.
__global__ void __launch_bounds__(256) k_agg(const int* __restrict__ src,
                                             float* __restrict__ out, int V)
{
    int gw = (blockIdx.x * 256 + threadIdx.x) >> 5;
    int lane = threadIdx.x & 31;
    if (gw >= V) return;
    int v = gw;
    int beg = g_rowptr[v], end = g_rowptr[v + 1];
    if (end <= beg) return;   // out already holds residual + bias

    float4 er4 = *reinterpret_cast<const float4*>(&g_er[v * HEADS]);

    int h = lane >> 3;
    float4 acc = make_float4(0.f, 0.f, 0.f, 0.f);
    float sacc = 0.0f;

    for (int base = beg; base < end; base += 32) {
        int n = end - base; if (n > 32) n = 32;
        int sv = 0;
        uint2 exu = make_uint2(0, 0);
        if (lane < n) {
            int eid = g_csr[base + lane];
            sv = __ldg(src + eid);
            float4 ee4 = *reinterpret_cast<const float4*>(&g_ee[(size_t)eid * HEADS]);
            float4 el4 = *reinterpret_cast<const float4*>(&g_el[sv * HEADS]);
            float t0 = el4.x + er4.x + ee4.x;
            float t1 = el4.y + er4.y + ee4.y;
            float t2 = el4.z + er4.z + ee4.z;
            float t3 = el4.w + er4.w + ee4.w;
            t0 = (t0 >= 0.f) ? t0 : NEG_SLOPE * t0;
            t1 = (t1 >= 0.f) ? t1 : NEG_SLOPE * t1;
            t2 = (t2 >= 0.f) ? t2 : NEG_SLOPE * t2;
            t3 = (t3 >= 0.f) ? t3 : NEG_SLOPE * t3;
            // shift-invariant softmax, O(1) logits -> exp directly; denom
            // accumulated locally (distributive), no atomics anywhere.
            __half2 h01 = __floats2half2_rn(__expf(t0), __expf(t1));
            __half2 h23 = __floats2half2_rn(__expf(t2), __expf(t3));
            exu.x = *reinterpret_cast<unsigned*>(&h01);
            exu.y = *reinterpret_cast<unsigned*>(&h23);
        }
        #pragma unroll 4
        for (int e = 0; e < n; e++) {
            int sve = __shfl_sync(0xFFFFFFFFu, sv, e);
            unsigned w0 = __shfl_sync(0xFFFFFFFFu, exu.x, e);
            unsigned w1 = __shfl_sync(0xFFFFFFFFu, exu.y, e);
            unsigned wh = (h < 2) ? w0 : w1;
            __half2 hp = *reinterpret_cast<__half2*>(&wh);
            float a = (h & 1) ? __high2float(hp) : __low2float(hp);
            uint2 u = __ldg(reinterpret_cast<const uint2*>(g_fth + (size_t)sve * HF + lane * 4));
            float2 f01 = __half22float2(*reinterpret_cast<__half2*>(&u.x));
            float2 f23 = __half22float2(*reinterpret_cast<__half2*>(&u.y));
            acc.x += a * f01.x; acc.y += a * f01.y;
            acc.z += a * f23.x; acc.w += a * f23.y;
            sacc += a;
        }
    }

    float inv = 1.0f / sacc;
    float4* op = reinterpret_cast<float4*>(out + (size_t)v * HF + lane * 4);
    float4 o = *op;
    o.x += acc.x * inv; o.y += acc.y * inv; o.z += acc.z * inv; o.w += acc.w * inv;
    *op = o;
}

// ---------------- launch: three-stream forked capture ----------------
static cudaStream_t g_s2 = nullptr, g_s3 = nullptr;
static cudaEvent_t g_evFork = nullptr, g_evJoin = nullptr, g_evFold = nullptr, g_evEE = nullptr;

extern "C" void kernel_launch(void* const* d_in, const int* in_sizes, int n_in,
                              void* d_out, int out_size)
{
    const float* nf   = (const float*)d_in[0];
    const float* ef   = (const float*)d_in[1];
    const int*   src  = (const int*)d_in[2];
    const int*   dst  = (const int*)d_in[3];
    const float* Wn   = (const float*)d_in[4];
    const float* We   = (const float*)d_in[5];
    const float* al   = (const float*)d_in[6];
    const float* ar   = (const float*)d_in[7];
    const float* ae   = (const float*)d_in[8];
    const float* Wr   = (const float*)d_in[9];
    const float* bias = (const float*)d_in[10];
    float* out = (float*)d_out;

    int V = in_sizes[0] / NODE_IN;
    int E = in_sizes[2];
    if (V > MAXV) V = MAXV;
    if (E > MAXE) E = MAXE;

    if (!g_s2) {
        cudaStreamCreateWithFlags(&g_s2, cudaStreamNonBlocking);
        cudaStreamCreateWithFlags(&g_s3, cudaStreamNonBlocking);
        cudaEventCreateWithFlags(&g_evFork, cudaEventDisableTiming);
        cudaEventCreateWithFlags(&g_evJoin, cudaEventDisableTiming);
        cudaEventCreateWithFlags(&g_evFold, cudaEventDisableTiming);
        cudaEventCreateWithFlags(&g_evEE, cudaEventDisableTiming);
    }

    const int smemProj = PROJ_ROWS * XS_LD * sizeof(float);   // ~33.8 KB
    int nch = (V + 1023) / 1024;
    int nq = (E + 3) / 4;

    cudaEventRecord(g_evFork, 0);
    cudaStreamWaitEvent(g_s2, g_evFork, 0);
    cudaStreamWaitEvent(g_s3, g_evFork, 0);

    k_fold<<<(NODE_IN * HF / 2 + 255) / 256, 256>>>(We, ae, Wn, Wr);  // #1 main
    cudaEventRecord(g_evFold, 0);

    // s3: ef-streaming edge GEMM, overlapped under nodeproj
    cudaStreamWaitEvent(g_s3, g_evFold, 0);
    k_ee<<<(E + 255) / 256, 256, 0, g_s3>>>(ef, E);                   // #2 s3
    cudaEventRecord(g_evEE, g_s3);

    // s2: CSR build
    k_zero<<<(V + 255) / 256, 256, 0, g_s2>>>(V);                     // #3 s2
    k_hist<<<(nq + 255) / 256, 256, 0, g_s2>>>(dst, E);               // #4 s2 (profiled)
    k_scan1<<<nch, 1024, 0, g_s2>>>(V);                               // #5 s2
    k_scan3<<<nch, 1024, 0, g_s2>>>(V);                               // #6 s2
    k_fill<<<(nq + 255) / 256, 256, 0, g_s2>>>(dst, E);               // #7 s2
    cudaEventRecord(g_evJoin, g_s2);

    // main chain
    k_nodeproj<<<(V + PROJ_ROWS - 1) / PROJ_ROWS, 256, smemProj>>>(nf, bias, al, ar, out, V);  // #8 main
    cudaStreamWaitEvent(0, g_evEE, 0);
    cudaStreamWaitEvent(0, g_evJoin, 0);
    k_agg<<<(V * 32 + 255) / 256, 256>>>(src, out, V);                // #9 main
}

// round 13
// speedup vs baseline: 2.0726x; 1.0079x over previous
#include <cuda_runtime.h>
#include <cuda_fp16.h>
#include <cstdint>

#define MAXV 50000
#define MAXE 800000
#define NODE_IN 128
#define EDGE_IN 16
#define HF 128
#define HEADS 4
#define OUTF 32
#define NEG_SLOPE 0.2f
#define PROJ_ROWS 64
#define XS_LD 132   // padded smem stride (floats) -> conflict-free A frags

// ---------------- device scratch ----------------
__device__ __half g_fth[MAXV * HF];     // projected node feats (fp16)
__device__ float g_ee[MAXE * HEADS];    // edge-feature logits (fp32)
__device__ float g_el[MAXV * HEADS];
__device__ float g_er[MAXV * HEADS];
__device__ int   g_deg[MAXV];           // zero-init; re-zeroed by k_agg each launch
__device__ int   g_incl[MAXV];
__device__ int   g_bsum[64];
__device__ int   g_rowptr[MAXV + 1];
__device__ int   g_cursor[MAXV];
__device__ int   g_csr[MAXE];
__device__ float g_wer[EDGE_IN * HEADS];
// pair-packed tf32 weights: index ((ks*HF + col)*4 + tig) -> (k=ks*8+tig, k+4)
__device__ uint2 g_wnr2[(NODE_IN / 8) * HF * 4];
__device__ uint2 g_wrr2[(NODE_IN / 8) * HF * 4];

__device__ __forceinline__ unsigned tf32r(float x) {
    unsigned u;
    asm("cvt.rna.tf32.f32 %0, %1;" : "=r"(u) : "f"(x));
    return u;
}

__device__ __forceinline__ void mma_tf32(float* d, const unsigned* a, const unsigned* b) {
    asm volatile(
        "mma.sync.aligned.m16n8k8.row.col.f32.tf32.tf32.f32 "
        "{%0,%1,%2,%3}, {%4,%5,%6,%7}, {%8,%9}, {%0,%1,%2,%3};"
        : "+f"(d[0]), "+f"(d[1]), "+f"(d[2]), "+f"(d[3])
        : "r"(a[0]), "r"(a[1]), "r"(a[2]), "r"(a[3]), "r"(b[0]), "r"(b[1]));
}

// ---------------- CSR-build kernels (side stream s2) ----------------
// 8 edges per thread for MLP (issue was 2.6% at 4/thread)
__global__ void k_hist(const int* __restrict__ dst, int E) {
    int i = blockIdx.x * blockDim.x + threadIdx.x;
    int b = i * 8;
    if (b + 7 < E) {
        int4 d4 = __ldg(reinterpret_cast<const int4*>(dst) + i * 2);
        int4 e4 = __ldg(reinterpret_cast<const int4*>(dst) + i * 2 + 1);
        atomicAdd(&g_deg[d4.x], 1);
        atomicAdd(&g_deg[d4.y], 1);
        atomicAdd(&g_deg[d4.z], 1);
        atomicAdd(&g_deg[d4.w], 1);
        atomicAdd(&g_deg[e4.x], 1);
        atomicAdd(&g_deg[e4.y], 1);
        atomicAdd(&g_deg[e4.z], 1);
        atomicAdd(&g_deg[e4.w], 1);
    } else {
        for (int j = b; j < E; j++) atomicAdd(&g_deg[dst[j]], 1);
    }
}

__global__ void k_scan1(int V) {
    __shared__ int wsum[32];
    int b = blockIdx.x, t = threadIdx.x;
    int i = b * 1024 + t;
    int val = (i < V) ? g_deg[i] : 0;
    int lane = t & 31, wid = t >> 5;
    int x = val;
    #pragma unroll
    for (int o = 1; o < 32; o <<= 1) {
        int y = __shfl_up_sync(0xFFFFFFFFu, x, o);
        if (lane >= o) x += y;
    }
    if (lane == 31) wsum[wid] = x;
    __syncthreads();
    if (wid == 0) {
        int s = wsum[lane];
        #pragma unroll
        for (int o = 1; o < 32; o <<= 1) {
            int y = __shfl_up_sync(0xFFFFFFFFu, s, o);
            if (lane >= o) s += y;
        }
        wsum[lane] = s;
    }
    __syncthreads();
    int incl = x + (wid > 0 ? wsum[wid - 1] : 0);
    if (i < V) g_incl[i] = incl;
    if (t == 1023) g_bsum[b] = incl;
}

__global__ void k_scan3(int V) {
    __shared__ int soff;
    int b = blockIdx.x, t = threadIdx.x;
    if (t < 32) {
        int s = 0;
        for (int j = t; j < b; j += 32) s += g_bsum[j];
        #pragma unroll
        for (int o = 16; o > 0; o >>= 1) s += __shfl_xor_sync(0xFFFFFFFFu, s, o);
        if (t == 0) soff = s;
    }
    __syncthreads();
    int i = b * 1024 + t;
    if (i < V) {
        int incl = g_incl[i] + soff;
        g_rowptr[i + 1] = incl;
        g_cursor[i] = incl - g_deg[i];
        if (i == 0) g_rowptr[0] = 0;
    }
}

// 8 edges per thread for MLP
__global__ void k_fill(const int* __restrict__ dst, int E) {
    int i = blockIdx.x * blockDim.x + threadIdx.x;
    int b = i * 8;
    if (b + 7 < E) {
        int4 d4 = __ldg(reinterpret_cast<const int4*>(dst) + i * 2);
        int4 e4 = __ldg(reinterpret_cast<const int4*>(dst) + i * 2 + 1);
        int p0 = atomicAdd(&g_cursor[d4.x], 1);
        int p1 = atomicAdd(&g_cursor[d4.y], 1);
        int p2 = atomicAdd(&g_cursor[d4.z], 1);
        int p3 = atomicAdd(&g_cursor[d4.w], 1);
        int p4 = atomicAdd(&g_cursor[e4.x], 1);
        int p5 = atomicAdd(&g_cursor[e4.y], 1);
        int p6 = atomicAdd(&g_cursor[e4.z], 1);
        int p7 = atomicAdd(&g_cursor[e4.w], 1);
        g_csr[p0] = b;     g_csr[p1] = b + 1;
        g_csr[p2] = b + 2; g_csr[p3] = b + 3;
        g_csr[p4] = b + 4; g_csr[p5] = b + 5;
        g_csr[p6] = b + 6; g_csr[p7] = b + 7;
    } else {
        for (int j = b; j < E; j++) {
            int pos = atomicAdd(&g_cursor[dst[j]], 1);
            g_csr[pos] = j;
        }
    }
}

// ---------------- fold + tf32 weight rounding into pair-packed layout ----
__global__ void k_fold(const float* __restrict__ We, const float* __restrict__ ae,
                       const float* __restrict__ Wn, const float* __restrict__ Wr) {
    int i = blockIdx.x * blockDim.x + threadIdx.x;
    int NP = (NODE_IN / 8) * HF * 4;     // 8192
    if (i < NP) {
        int ks  = i >> 9;                // /(HF*4)
        int col = (i >> 2) & (HF - 1);
        int tig = i & 3;
        int k0 = ks * 8 + tig;
        g_wnr2[i] = make_uint2(tf32r(Wn[(size_t)k0 * HF + col]),
                               tf32r(Wn[(size_t)(k0 + 4) * HF + col]));
        g_wrr2[i] = make_uint2(tf32r(Wr[(size_t)k0 * HF + col]),
                               tf32r(Wr[(size_t)(k0 + 4) * HF + col]));
    }
    if (blockIdx.x == 0 && threadIdx.x < EDGE_IN * HEADS) {
        int t = threadIdx.x;
        int j = t >> 2, h = t & 3;
        float s = 0.0f;
        #pragma unroll
        for (int f = 0; f < OUTF; f++)
            s += We[j * HF + h * OUTF + f] * ae[h * OUTF + f];
        g_wer[j * HEADS + h] = s;
    }
}

// ---------------- edge-feature logits (stream s3, overlaps nodeproj) -----
__global__ void __launch_bounds__(256) k_ee(const float* __restrict__ ef, int E)
{
    __shared__ float swer[EDGE_IN * HEADS];
    __shared__ float sef[256 * 17];     // stride-17 pad -> conflict-free reads

    if (threadIdx.x < EDGE_IN * HEADS) swer[threadIdx.x] = g_wer[threadIdx.x];

    int base = blockIdx.x * 256;
    int nEdge = E - base; if (nEdge > 256) nEdge = 256;

    int nF4 = nEdge * 4;                // 16 floats per edge / 4
    const float4* efp = reinterpret_cast<const float4*>(ef) + (size_t)base * 4;
    for (int i = threadIdx.x; i < nF4; i += 256) {
        float4 f = __ldg(efp + i);
        int e = i >> 2, j0 = (i & 3) * 4;
        float* p = &sef[e * 17 + j0];
        p[0] = f.x; p[1] = f.y; p[2] = f.z; p[3] = f.w;
    }
    __syncthreads();

    int t = threadIdx.x;
    if (t >= nEdge) return;

    const float* row = &sef[t * 17];
    float ee0 = 0.f, ee1 = 0.f, ee2 = 0.f, ee3 = 0.f;
    #pragma unroll
    for (int j = 0; j < EDGE_IN; j++) {
        float e = row[j];
        ee0 += e * swer[j * 4 + 0];
        ee1 += e * swer[j * 4 + 1];
        ee2 += e * swer[j * 4 + 2];
        ee3 += e * swer[j * 4 + 3];
    }
    *reinterpret_cast<float4*>(&g_ee[(size_t)(base + t) * HEADS]) =
        make_float4(ee0, ee1, ee2, ee3);
}

// ---------------- node projection via TF32 HMMA ----------------
__global__ void __launch_bounds__(256, 2) k_nodeproj(
    const float* __restrict__ nf, const float* __restrict__ bias,
    const float* __restrict__ al, const float* __restrict__ ar,
    float* __restrict__ out, int V)
{
    extern __shared__ float xs[];   // [64][XS_LD]
    int v0 = blockIdx.x * PROJ_ROWS;
    int tid = threadIdx.x;

    #pragma unroll
    for (int i = 0; i < 8; i++) {
        int idx = tid + i * 256;
        int r = idx >> 5;
        int c4 = idx & 31;
        int v = v0 + r;
        float4 val = make_float4(0.f, 0.f, 0.f, 0.f);
        if (v < V) val = *reinterpret_cast<const float4*>(nf + (size_t)v * NODE_IN + c4 * 4);
        val.x = __uint_as_float(tf32r(val.x));
        val.y = __uint_as_float(tf32r(val.y));
        val.z = __uint_as_float(tf32r(val.z));
        val.w = __uint_as_float(tf32r(val.w));
        *reinterpret_cast<float4*>(&xs[r * XS_LD + c4 * 4]) = val;
    }
    __syncthreads();

    int lane = tid & 31;
    int warp = tid >> 5;
    int wrow = warp & 1;
    int wcg  = warp >> 1;
    int tig  = lane & 3;
    int gid  = lane >> 2;

    const uint2* B2 = (wcg < 2) ? g_wnr2 : g_wrr2;
    int nb = (wcg & 1) * 64;
    int mbase = wrow * 32;

    float acc[2][8][4];
    #pragma unroll
    for (int mt = 0; mt < 2; mt++)
        #pragma unroll
        for (int nt = 0; nt < 8; nt++)
            #pragma unroll
            for (int q = 0; q < 4; q++) acc[mt][nt][q] = 0.f;

    #pragma unroll 2
    for (int ks = 0; ks < 16; ks++) {
        int kb = ks * 8;
        unsigned a[2][4];
        #pragma unroll
        for (int mt = 0; mt < 2; mt++) {
            int r0 = mbase + mt * 16 + gid;
            a[mt][0] = __float_as_uint(xs[r0 * XS_LD + kb + tig]);
            a[mt][1] = __float_as_uint(xs[(r0 + 8) * XS_LD + kb + tig]);
            a[mt][2] = __float_as_uint(xs[r0 * XS_LD + kb + tig + 4]);
            a[mt][3] = __float_as_uint(xs[(r0 + 8) * XS_LD + kb + tig + 4]);
        }
        unsigned b[8][2];
        #pragma unroll
        for (int nt = 0; nt < 8; nt++) {
            int col = nb + nt * 8 + gid;
            uint2 bp = __ldg(&B2[(ks * HF + col) * 4 + tig]);
            b[nt][0] = bp.x;
            b[nt][1] = bp.y;
        }
        #pragma unroll
        for (int mt = 0; mt < 2; mt++)
            #pragma unroll
            for (int nt = 0; nt < 8; nt++)
                mma_tf32(acc[mt][nt], a[mt], b[nt]);
    }

    if (wcg < 2) {
        float2 alf[8], arf[8];
        #pragma unroll
        for (int nt = 0; nt < 8; nt++) {
            int h = wcg * 2 + (nt >> 2);
            int off = h * OUTF + (nt & 3) * 8 + 2 * tig;
            alf[nt] = *reinterpret_cast<const float2*>(al + off);
            arf[nt] = *reinterpret_cast<const float2*>(ar + off);
        }
        #pragma unroll
        for (int mt = 0; mt < 2; mt++) {
            int r0 = v0 + mbase + mt * 16 + gid;
            float el0[2] = {0.f, 0.f}, el1[2] = {0.f, 0.f};
            float er0[2] = {0.f, 0.f}, er1[2] = {0.f, 0.f};
            #pragma unroll
            for (int nt = 0; nt < 8; nt++) {
                int hh = nt >> 2;
                el0[hh] += acc[mt][nt][0] * alf[nt].x + acc[mt][nt][1] * alf[nt].y;
                el1[hh] += acc[mt][nt][2] * alf[nt].x + acc[mt][nt][3] * alf[nt].y;
                er0[hh] += acc[mt][nt][0] * arf[nt].x + acc[mt][nt][1] * arf[nt].y;
                er1[hh] += acc[mt][nt][2] * arf[nt].x + acc[mt][nt][3] * arf[nt].y;
                int col = wcg * 64 + nt * 8 + 2 * tig;
                if (r0 < V)
                    *reinterpret_cast<__half2*>(g_fth + (size_t)r0 * HF + col)
                        = __floats2half2_rn(acc[mt][nt][0], acc[mt][nt][1]);
                if (r0 + 8 < V)
                    *reinterpret_cast<__half2*>(g_fth + (size_t)(r0 + 8) * HF + col)
                        = __floats2half2_rn(acc[mt][nt][2], acc[mt][nt][3]);
            }
            #pragma unroll
            for (int hh = 0; hh < 2; hh++) {
                float a0 = el0[hh], a1 = el1[hh], b0 = er0[hh], b1 = er1[hh];
                a0 += __shfl_xor_sync(0xFFFFFFFFu, a0, 1); a0 += __shfl_xor_sync(0xFFFFFFFFu, a0, 2);
                a1 += __shfl_xor_sync(0xFFFFFFFFu, a1, 1); a1 += __shfl_xor_sync(0xFFFFFFFFu, a1, 2);
                b0 += __shfl_xor_sync(0xFFFFFFFFu, b0, 1); b0 += __shfl_xor_sync(0xFFFFFFFFu, b0, 2);
                b1 += __shfl_xor_sync(0xFFFFFFFFu, b1, 1); b1 += __shfl_xor_sync(0xFFFFFFFFu, b1, 2);
                int h = wcg * 2 + hh;
                if (tig == 0) {
                    if (r0 < V)     { g_el[r0 * HEADS + h] = a0;       g_er[r0 * HEADS + h] = b0; }
                    if (r0 + 8 < V) { g_el[(r0 + 8) * HEADS + h] = a1; g_er[(r0 + 8) * HEADS + h] = b1; }
                }
            }
        }
    } else {
        int cb = (wcg - 2) * 64;
        float2 bv[8];
        #pragma unroll
        for (int nt = 0; nt < 8; nt++)
            bv[nt] = *reinterpret_cast<const float2*>(bias + cb + nt * 8 + 2 * tig);
        #pragma unroll
        for (int mt = 0; mt < 2; mt++) {
            int r0 = v0 + mbase + mt * 16 + gid;
            #pragma unroll
            for (int nt = 0; nt < 8; nt++) {
                int col = cb + nt * 8 + 2 * tig;
                if (r0 < V)
                    *reinterpret_cast<float2*>(out + (size_t)r0 * HF + col)
                        = make_float2(acc[mt][nt][0] + bv[nt].x, acc[mt][nt][1] + bv[nt].y);
                if (r0 + 8 < V)
                    *reinterpret_cast<float2*>(out + (size_t)(r0 + 8) * HF + col)
                        = make_float2(acc[mt][nt][2] + bv[nt].x, acc[mt][nt][3] + bv[nt].y);
            }
        }
    }
}

// ---------------- aggregation: one warp per dst, fused exp ----------------
__global__ void __launch_bounds__(256) k_agg(const int* __restrict__ src,
                                             float* __restrict__ out, int V)
{
    int gw = (blockIdx.x * 256 + threadIdx.x) >> 5;
    int lane = threadIdx.x & 31;
    if (gw >= V) return;
    int v = gw;
    int beg = g_rowptr[v], end = g_rowptr[v + 1];
    if (end <= beg) return;   // out already holds residual + bias; deg[v]==0 already

    if (lane == 0) g_deg[v] = 0;   // reset for next launch (replay-clean)

    float4 er4 = *reinterpret_cast<const float4*>(&g_er[v * HEADS]);

    int h = lane >> 3;
    float4 acc = make_float4(0.f, 0.f, 0.f, 0.f);
    float sacc = 0.0f;

    for (int base = beg; base < end; base += 32) {
        int n = end - base; if (n > 32) n = 32;
        int sv = 0;
        uint2 exu = make_uint2(0, 0);
        if (lane < n) {
            int eid = g_csr[base + lane];
            sv = __ldg(src + eid);
            float4 ee4 = *reinterpret_cast<const float4*>(&g_ee[(size_t)eid * HEADS]);
            float4 el4 = *reinterpret_cast<const float4*>(&g_el[sv * HEADS]);
            float t0 = el4.x + er4.x + ee4.x;
            float t1 = el4.y + er4.y + ee4.y;
            float t2 = el4.z + er4.z + ee4.z;
            float t3 = el4.w + er4.w + ee4.w;
            t0 = (t0 >= 0.f) ? t0 : NEG_SLOPE * t0;
            t1 = (t1 >= 0.f) ? t1 : NEG_SLOPE * t1;
            t2 = (t2 >= 0.f) ? t2 : NEG_SLOPE * t2;
            t3 = (t3 >= 0.f) ? t3 : NEG_SLOPE * t3;
            // shift-invariant softmax, O(1) logits -> exp directly; denom
            // accumulated locally (distributive), no atomics anywhere.
            __half2 h01 = __floats2half2_rn(__expf(t0), __expf(t1));
            __half2 h23 = __floats2half2_rn(__expf(t2), __expf(t3));
            exu.x = *reinterpret_cast<unsigned*>(&h01);
            exu.y = *reinterpret_cast<unsigned*>(&h23);
        }
        #pragma unroll 4
        for (int e = 0; e < n; e++) {
            int sve = __shfl_sync(0xFFFFFFFFu, sv, e);
            unsigned w0 = __shfl_sync(0xFFFFFFFFu, exu.x, e);
            unsigned w1 = __shfl_sync(0xFFFFFFFFu, exu.y, e);
            unsigned wh = (h < 2) ? w0 : w1;
            __half2 hp = *reinterpret_cast<__half2*>(&wh);
            float a = (h & 1) ? __high2float(hp) : __low2float(hp);
            uint2 u = __ldg(reinterpret_cast<const uint2*>(g_fth + (size_t)sve * HF + lane * 4));
            float2 f01 = __half22float2(*reinterpret_cast<__half2*>(&u.x));
            float2 f23 = __half22float2(*reinterpret_cast<__half2*>(&u.y));
            acc.x += a * f01.x; acc.y += a * f01.y;
            acc.z += a * f23.x; acc.w += a * f23.y;
            sacc += a;
        }
    }

    float inv = 1.0f / sacc;
    float4* op = reinterpret_cast<float4*>(out + (size_t)v * HF + lane * 4);
    float4 o = *op;
    o.x += acc.x * inv; o.y += acc.y * inv; o.z += acc.z * inv; o.w += acc.w * inv;
    *op = o;
}

// ---------------- launch: three-stream forked capture ----------------
static cudaStream_t g_s2 = nullptr, g_s3 = nullptr;
static cudaEvent_t g_evFork = nullptr, g_evJoin = nullptr, g_evFold = nullptr, g_evEE = nullptr;

extern "C" void kernel_launch(void* const* d_in, const int* in_sizes, int n_in,
                              void* d_out, int out_size)
{
    const float* nf   = (const float*)d_in[0];
    const float* ef   = (const float*)d_in[1];
    const int*   src  = (const int*)d_in[2];
    const int*   dst  = (const int*)d_in[3];
    const float* Wn   = (const float*)d_in[4];
    const float* We   = (const float*)d_in[5];
    const float* al   = (const float*)d_in[6];
    const float* ar   = (const float*)d_in[7];
    const float* ae   = (const float*)d_in[8];
    const float* Wr   = (const float*)d_in[9];
    const float* bias = (const float*)d_in[10];
    float* out = (float*)d_out;

    int V = in_sizes[0] / NODE_IN;
    int E = in_sizes[2];
    if (V > MAXV) V = MAXV;
    if (E > MAXE) E = MAXE;

    if (!g_s2) {
        cudaStreamCreateWithFlags(&g_s2, cudaStreamNonBlocking);
        cudaStreamCreateWithFlags(&g_s3, cudaStreamNonBlocking);
        cudaEventCreateWithFlags(&g_evFork, cudaEventDisableTiming);
        cudaEventCreateWithFlags(&g_evJoin, cudaEventDisableTiming);
        cudaEventCreateWithFlags(&g_evFold, cudaEventDisableTiming);
        cudaEventCreateWithFlags(&g_evEE, cudaEventDisableTiming);
    }

    const int smemProj = PROJ_ROWS * XS_LD * sizeof(float);   // ~33.8 KB
    int nch = (V + 1023) / 1024;
    int no = (E + 7) / 8;

    cudaEventRecord(g_evFork, 0);
    cudaStreamWaitEvent(g_s2, g_evFork, 0);
    cudaStreamWaitEvent(g_s3, g_evFork, 0);

    k_fold<<<(NODE_IN * HF / 2 + 255) / 256, 256>>>(We, ae, Wn, Wr);  // #1 main
    cudaEventRecord(g_evFold, 0);

    // s3: ef-streaming edge GEMM, overlapped under nodeproj
    cudaStreamWaitEvent(g_s3, g_evFold, 0);
    k_ee<<<(E + 255) / 256, 256, 0, g_s3>>>(ef, E);                   // #2 s3
    cudaEventRecord(g_evEE, g_s3);

    // s2: CSR build (g_deg pre-zeroed by previous k_agg / initial zero-init)
    k_hist<<<(no + 255) / 256, 256, 0, g_s2>>>(dst, E);               // #3 s2
    // main chain: nodeproj in profiled slot #4
    k_nodeproj<<<(V + PROJ_ROWS - 1) / PROJ_ROWS, 256, smemProj>>>(nf, bias, al, ar, out, V);  // #4 main (profiled)
    k_scan1<<<nch, 1024, 0, g_s2>>>(V);                               // #5 s2
    k_scan3<<<nch, 1024, 0, g_s2>>>(V);                               // #6 s2
    k_fill<<<(no + 255) / 256, 256, 0, g_s2>>>(dst, E);               // #7 s2
    cudaEventRecord(g_evJoin, g_s2);

    cudaStreamWaitEvent(0, g_evEE, 0);
    cudaStreamWaitEvent(0, g_evJoin, 0);
    k_agg<<<(V * 32 + 255) / 256, 256>>>(src, out, V);                // #8 main
}

// round 14
// speedup vs baseline: 2.1829x; 1.0532x over previous
#include <cuda_runtime.h>
#include <cuda_fp16.h>
#include <cstdint>

#define MAXV 50000
#define MAXE 800000
#define NODE_IN 128
#define EDGE_IN 16
#define HF 128
#define HEADS 4
#define OUTF 32
#define NEG_SLOPE 0.2f
#define PROJ_ROWS 64
#define XS_LD 132   // padded smem stride (floats) -> conflict-free A frags

// ---------------- device scratch ----------------
__device__ __half g_fth[MAXV * HF];     // projected node feats (fp16)
__device__ float g_ee[MAXE * HEADS];    // edge-feature logits (fp32)
__device__ float g_el[MAXV * HEADS];
__device__ float g_er[MAXV * HEADS];
__device__ int   g_deg[MAXV];           // zero-init; re-zeroed by k_agg each launch
__device__ int   g_incl[MAXV];
__device__ int   g_bsum[64];
__device__ int   g_rowptr[MAXV + 1];
__device__ int   g_cursor[MAXV];
__device__ int   g_csr[MAXE];
__device__ float g_wer[EDGE_IN * HEADS];
__device__ int   g_barCnt;              // zero-init; reset by each barrier pass
__device__ int   g_barGen;              // monotonically increasing across replays
// pair-packed tf32 weights: index ((ks*HF + col)*4 + tig) -> (k=ks*8+tig, k+4)
__device__ uint2 g_wnr2[(NODE_IN / 8) * HF * 4];
__device__ uint2 g_wrr2[(NODE_IN / 8) * HF * 4];

__device__ __forceinline__ unsigned tf32r(float x) {
    unsigned u;
    asm("cvt.rna.tf32.f32 %0, %1;" : "=r"(u) : "f"(x));
    return u;
}

__device__ __forceinline__ void mma_tf32(float* d, const unsigned* a, const unsigned* b) {
    asm volatile(
        "mma.sync.aligned.m16n8k8.row.col.f32.tf32.tf32.f32 "
        "{%0,%1,%2,%3}, {%4,%5,%6,%7}, {%8,%9}, {%0,%1,%2,%3};"
        : "+f"(d[0]), "+f"(d[1]), "+f"(d[2]), "+f"(d[3])
        : "r"(a[0]), "r"(a[1]), "r"(a[2]), "r"(a[3]), "r"(b[0]), "r"(b[1]));
}

// spin grid barrier: all blocks resident (grid = 49 <= 148 SMs) -> safe
__device__ __forceinline__ void gridBarrier(int nblk) {
    __syncthreads();
    if (threadIdx.x == 0) {
        volatile int* vgen = &g_barGen;
        int gen = *vgen;
        __threadfence();
        if (atomicAdd(&g_barCnt, 1) == nblk - 1) {
            g_barCnt = 0;
            __threadfence();
            atomicAdd(&g_barGen, 1);
        } else {
            while (*vgen == gen) { }
        }
    }
    __syncthreads();
}

// ---------------- fused CSR build: hist -> scan -> fill (one kernel) -----
__global__ void __launch_bounds__(1024) k_csr(const int* __restrict__ dst, int E, int V)
{
    int nblk = gridDim.x;
    int gtid = blockIdx.x * 1024 + threadIdx.x;
    int nth = nblk * 1024;

    // phase 1: histogram (g_deg pre-zeroed by previous k_agg / initial init)
    int nq4 = E >> 2;
    for (int i = gtid; i < nq4; i += nth) {
        int4 d4 = __ldg(reinterpret_cast<const int4*>(dst) + i);
        atomicAdd(&g_deg[d4.x], 1);
        atomicAdd(&g_deg[d4.y], 1);
        atomicAdd(&g_deg[d4.z], 1);
        atomicAdd(&g_deg[d4.w], 1);
    }
    if (gtid == 0)
        for (int j = nq4 * 4; j < E; j++) atomicAdd(&g_deg[dst[j]], 1);

    gridBarrier(nblk);

    // phase 2: per-block inclusive scan (block b covers [b*1024, b*1024+1024))
    {
        __shared__ int wsum[32];
        int b = blockIdx.x, t = threadIdx.x;
        int i = b * 1024 + t;
        int val = (i < V) ? g_deg[i] : 0;
        int lane = t & 31, wid = t >> 5;
        int x = val;
        #pragma unroll
        for (int o = 1; o < 32; o <<= 1) {
            int y = __shfl_up_sync(0xFFFFFFFFu, x, o);
            if (lane >= o) x += y;
        }
        if (lane == 31) wsum[wid] = x;
        __syncthreads();
        if (wid == 0) {
            int s = wsum[lane];
            #pragma unroll
            for (int o = 1; o < 32; o <<= 1) {
                int y = __shfl_up_sync(0xFFFFFFFFu, s, o);
                if (lane >= o) s += y;
            }
            wsum[lane] = s;
        }
        __syncthreads();
        int incl = x + (wid > 0 ? wsum[wid - 1] : 0);
        if (i < V) g_incl[i] = incl;
        if (t == 1023) g_bsum[b] = incl;
    }

    gridBarrier(nblk);

    // phase 3: cross-block prefix + rowptr/cursor
    {
        __shared__ int soff;
        int b = blockIdx.x, t = threadIdx.x;
        if (t < 32) {
            int s = 0;
            for (int j = t; j < b; j += 32) s += g_bsum[j];
            #pragma unroll
            for (int o = 16; o > 0; o >>= 1) s += __shfl_xor_sync(0xFFFFFFFFu, s, o);
            if (t == 0) soff = s;
        }
        __syncthreads();
        int i = b * 1024 + t;
        if (i < V) {
            int incl = g_incl[i] + soff;
            g_rowptr[i + 1] = incl;
            g_cursor[i] = incl - g_deg[i];
            if (i == 0) g_rowptr[0] = 0;
        }
    }

    gridBarrier(nblk);

    // phase 4: fill CSR
    for (int i = gtid; i < nq4; i += nth) {
        int4 d4 = __ldg(reinterpret_cast<const int4*>(dst) + i);
        int b = i * 4;
        int p0 = atomicAdd(&g_cursor[d4.x], 1);
        int p1 = atomicAdd(&g_cursor[d4.y], 1);
        int p2 = atomicAdd(&g_cursor[d4.z], 1);
        int p3 = atomicAdd(&g_cursor[d4.w], 1);
        g_csr[p0] = b;
        g_csr[p1] = b + 1;
        g_csr[p2] = b + 2;
        g_csr[p3] = b + 3;
    }
    if (gtid == 0)
        for (int j = nq4 * 4; j < E; j++) {
            int pos = atomicAdd(&g_cursor[dst[j]], 1);
            g_csr[pos] = j;
        }
}

// ---------------- fold + tf32 weight rounding into pair-packed layout ----
__global__ void k_fold(const float* __restrict__ We, const float* __restrict__ ae,
                       const float* __restrict__ Wn, const float* __restrict__ Wr) {
    int i = blockIdx.x * blockDim.x + threadIdx.x;
    int NP = (NODE_IN / 8) * HF * 4;     // 8192
    if (i < NP) {
        int ks  = i >> 9;                // /(HF*4)
        int col = (i >> 2) & (HF - 1);
        int tig = i & 3;
        int k0 = ks * 8 + tig;
        g_wnr2[i] = make_uint2(tf32r(Wn[(size_t)k0 * HF + col]),
                               tf32r(Wn[(size_t)(k0 + 4) * HF + col]));
        g_wrr2[i] = make_uint2(tf32r(Wr[(size_t)k0 * HF + col]),
                               tf32r(Wr[(size_t)(k0 + 4) * HF + col]));
    }
    if (blockIdx.x == 0 && threadIdx.x < EDGE_IN * HEADS) {
        int t = threadIdx.x;
        int j = t >> 2, h = t & 3;
        float s = 0.0f;
        #pragma unroll
        for (int f = 0; f < OUTF; f++)
            s += We[j * HF + h * OUTF + f] * ae[h * OUTF + f];
        g_wer[j * HEADS + h] = s;
    }
}

// ---------------- edge-feature logits (stream s3, overlaps nodeproj) -----
__global__ void __launch_bounds__(256) k_ee(const float* __restrict__ ef, int E)
{
    __shared__ float swer[EDGE_IN * HEADS];
    __shared__ float sef[256 * 17];     // stride-17 pad -> conflict-free reads

    if (threadIdx.x < EDGE_IN * HEADS) swer[threadIdx.x] = g_wer[threadIdx.x];

    int base = blockIdx.x * 256;
    int nEdge = E - base; if (nEdge > 256) nEdge = 256;

    int nF4 = nEdge * 4;                // 16 floats per edge / 4
    const float4* efp = reinterpret_cast<const float4*>(ef) + (size_t)base * 4;
    for (int i = threadIdx.x; i < nF4; i += 256) {
        float4 f = __ldg(efp + i);
        int e = i >> 2, j0 = (i & 3) * 4;
        float* p = &sef[e * 17 + j0];
        p[0] = f.x; p[1] = f.y; p[2] = f.z; p[3] = f.w;
    }
    __syncthreads();

    int t = threadIdx.x;
    if (t >= nEdge) return;

    const float* row = &sef[t * 17];
    float ee0 = 0.f, ee1 = 0.f, ee2 = 0.f, ee3 = 0.f;
    #pragma unroll
    for (int j = 0; j < EDGE_IN; j++) {
        float e = row[j];
        ee0 += e * swer[j * 4 + 0];
        ee1 += e * swer[j * 4 + 1];
        ee2 += e * swer[j * 4 + 2];
        ee3 += e * swer[j * 4 + 3];
    }
    *reinterpret_cast<float4*>(&g_ee[(size_t)(base + t) * HEADS]) =
        make_float4(ee0, ee1, ee2, ee3);
}

// ---------------- node projection via TF32 HMMA ----------------
__global__ void __launch_bounds__(256, 2) k_nodeproj(
    const float* __restrict__ nf, const float* __restrict__ bias,
    const float* __restrict__ al, const float* __restrict__ ar,
    float* __restrict__ out, int V)
{
    extern __shared__ float xs[];   // [64][XS_LD]
    int v0 = blockIdx.x * PROJ_ROWS;
    int tid = threadIdx.x;

    #pragma unroll
    for (int i = 0; i < 8; i++) {
        int idx = tid + i * 256;
        int r = idx >> 5;
        int c4 = idx & 31;
        int v = v0 + r;
        float4 val = make_float4(0.f, 0.f, 0.f, 0.f);
        if (v < V) val = *reinterpret_cast<const float4*>(nf + (size_t)v * NODE_IN + c4 * 4);
        val.x = __uint_as_float(tf32r(val.x));
        val.y = __uint_as_float(tf32r(val.y));
        val.z = __uint_as_float(tf32r(val.z));
        val.w = __uint_as_float(tf32r(val.w));
        *reinterpret_cast<float4*>(&xs[r * XS_LD + c4 * 4]) = val;
    }
    __syncthreads();

    int lane = tid & 31;
    int warp = tid >> 5;
    int wrow = warp & 1;
    int wcg  = warp >> 1;
    int tig  = lane & 3;
    int gid  = lane >> 2;

    const uint2* B2 = (wcg < 2) ? g_wnr2 : g_wrr2;
    int nb = (wcg & 1) * 64;
    int mbase = wrow * 32;

    float acc[2][8][4];
    #pragma unroll
    for (int mt = 0; mt < 2; mt++)
        #pragma unroll
        for (int nt = 0; nt < 8; nt++)
            #pragma unroll
            for (int q = 0; q < 4; q++) acc[mt][nt][q] = 0.f;

    #pragma unroll 2
    for (int ks = 0; ks < 16; ks++) {
        int kb = ks * 8;
        unsigned a[2][4];
        #pragma unroll
        for (int mt = 0; mt < 2; mt++) {
            int r0 = mbase + mt * 16 + gid;
            a[mt][0] = __float_as_uint(xs[r0 * XS_LD + kb + tig]);
            a[mt][1] = __float_as_uint(xs[(r0 + 8) * XS_LD + kb + tig]);
            a[mt][2] = __float_as_uint(xs[r0 * XS_LD + kb + tig + 4]);
            a[mt][3] = __float_as_uint(xs[(r0 + 8) * XS_LD + kb + tig + 4]);
        }
        unsigned b[8][2];
        #pragma unroll
        for (int nt = 0; nt < 8; nt++) {
            int col = nb + nt * 8 + gid;
            uint2 bp = __ldg(&B2[(ks * HF + col) * 4 + tig]);
            b[nt][0] = bp.x;
            b[nt][1] = bp.y;
        }
        #pragma unroll
        for (int mt = 0; mt < 2; mt++)
            #pragma unroll
            for (int nt = 0; nt < 8; nt++)
                mma_tf32(acc[mt][nt], a[mt], b[nt]);
    }

    if (wcg < 2) {
        float2 alf[8], arf[8];
        #pragma unroll
        for (int nt = 0; nt < 8; nt++) {
            int h = wcg * 2 + (nt >> 2);
            int off = h * OUTF + (nt & 3) * 8 + 2 * tig;
            alf[nt] = *reinterpret_cast<const float2*>(al + off);
            arf[nt] = *reinterpret_cast<const float2*>(ar + off);
        }
        #pragma unroll
        for (int mt = 0; mt < 2; mt++) {
            int r0 = v0 + mbase + mt * 16 + gid;
            float el0[2] = {0.f, 0.f}, el1[2] = {0.f, 0.f};
            float er0[2] = {0.f, 0.f}, er1[2] = {0.f, 0.f};
            #pragma unroll
            for (int nt = 0; nt < 8; nt++) {
                int hh = nt >> 2;
                el0[hh] += acc[mt][nt][0] * alf[nt].x + acc[mt][nt][1] * alf[nt].y;
                el1[hh] += acc[mt][nt][2] * alf[nt].x + acc[mt][nt][3] * alf[nt].y;
                er0[hh] += acc[mt][nt][0] * arf[nt].x + acc[mt][nt][1] * arf[nt].y;
                er1[hh] += acc[mt][nt][2] * arf[nt].x + acc[mt][nt][3] * arf[nt].y;
                int col = wcg * 64 + nt * 8 + 2 * tig;
                if (r0 < V)
                    *reinterpret_cast<__half2*>(g_fth + (size_t)r0 * HF + col)
                        = __floats2half2_rn(acc[mt][nt][0], acc[mt][nt][1]);
                if (r0 + 8 < V)
                    *reinterpret_cast<__half2*>(g_fth + (size_t)(r0 + 8) * HF + col)
                        = __floats2half2_rn(acc[mt][nt][2], acc[mt][nt][3]);
            }
            #pragma unroll
            for (int hh = 0; hh < 2; hh++) {
                float a0 = el0[hh], a1 = el1[hh], b0 = er0[hh], b1 = er1[hh];
                a0 += __shfl_xor_sync(0xFFFFFFFFu, a0, 1); a0 += __shfl_xor_sync(0xFFFFFFFFu, a0, 2);
                a1 += __shfl_xor_sync(0xFFFFFFFFu, a1, 1); a1 += __shfl_xor_sync(0xFFFFFFFFu, a1, 2);
                b0 += __shfl_xor_sync(0xFFFFFFFFu, b0, 1); b0 += __shfl_xor_sync(0xFFFFFFFFu, b0, 2);
                b1 += __shfl_xor_sync(0xFFFFFFFFu, b1, 1); b1 += __shfl_xor_sync(0xFFFFFFFFu, b1, 2);
                int h = wcg * 2 + hh;
                if (tig == 0) {
                    if (r0 < V)     { g_el[r0 * HEADS + h] = a0;       g_er[r0 * HEADS + h] = b0; }
                    if (r0 + 8 < V) { g_el[(r0 + 8) * HEADS + h] = a1; g_er[(r0 + 8) * HEADS + h] = b1; }
                }
            }
        }
    } else {
        int cb = (wcg - 2) * 64;
        float2 bv[8];
        #pragma unroll
        for (int nt = 0; nt < 8; nt++)
            bv[nt] = *reinterpret_cast<const float2*>(bias + cb + nt * 8 + 2 * tig);
        #pragma unroll
        for (int mt = 0; mt < 2; mt++) {
            int r0 = v0 + mbase + mt * 16 + gid;
            #pragma unroll
            for (int nt = 0; nt < 8; nt++) {
                int col = cb + nt * 8 + 2 * tig;
                if (r0 < V)
                    *reinterpret_cast<float2*>(out + (size_t)r0 * HF + col)
                        = make_float2(acc[mt][nt][0] + bv[nt].x, acc[mt][nt][1] + bv[nt].y);
                if (r0 + 8 < V)
                    *reinterpret_cast<float2*>(out + (size_t)(r0 + 8) * HF + col)
                        = make_float2(acc[mt][nt][2] + bv[nt].x, acc[mt][nt][3] + bv[nt].y);
            }
        }
    }
}

// ---------------- aggregation: one warp per dst, fused exp ----------------
__global__ void __launch_bounds__(256) k_agg(const int* __restrict__ src,
                                             float* __restrict__ out, int V)
{
    int gw = (blockIdx.x * 256 + threadIdx.x) >> 5;
    int lane = threadIdx.x & 31;
    if (gw >= V) return;
    int v = gw;
    int beg = g_rowptr[v], end = g_rowptr[v + 1];
    if (end <= beg) return;   // out already holds residual + bias; deg[v]==0 already

    if (lane == 0) g_deg[v] = 0;   // reset for next launch (replay-clean)

    float4 er4 = *reinterpret_cast<const float4*>(&g_er[v * HEADS]);

    int h = lane >> 3;
    float4 acc = make_float4(0.f, 0.f, 0.f, 0.f);
    float sacc = 0.0f;

    for (int base = beg; base < end; base += 32) {
        int n = end - base; if (n > 32) n = 32;
        int sv = 0;
        uint2 exu = make_uint2(0, 0);
        if (lane < n) {
            int eid = g_csr[base + lane];
            sv = __ldg(src + eid);
            float4 ee4 = *reinterpret_cast<const float4*>(&g_ee[(size_t)eid * HEADS]);
            float4 el4 = *reinterpret_cast<const float4*>(&g_el[sv * HEADS]);
            float t0 = el4.x + er4.x + ee4.x;
            float t1 = el4.y + er4.y + ee4.y;
            float t2 = el4.z + er4.z + ee4.z;
            float t3 = el4.w + er4.w + ee4.w;
            t0 = (t0 >= 0.f) ? t0 : NEG_SLOPE * t0;
            t1 = (t1 >= 0.f) ? t1 : NEG_SLOPE * t1;
            t2 = (t2 >= 0.f) ? t2 : NEG_SLOPE * t2;
            t3 = (t3 >= 0.f) ? t3 : NEG_SLOPE * t3;
            // shift-invariant softmax, O(1) logits -> exp directly; denom
            // accumulated locally (distributive), no atomics anywhere.
            __half2 h01 = __floats2half2_rn(__expf(t0), __expf(t1));
            __half2 h23 = __floats2half2_rn(__expf(t2), __expf(t3));
            exu.x = *reinterpret_cast<unsigned*>(&h01);
            exu.y = *reinterpret_cast<unsigned*>(&h23);
        }
        #pragma unroll 4
        for (int e = 0; e < n; e++) {
            int sve = __shfl_sync(0xFFFFFFFFu, sv, e);
            unsigned w0 = __shfl_sync(0xFFFFFFFFu, exu.x, e);
            unsigned w1 = __shfl_sync(0xFFFFFFFFu, exu.y, e);
            unsigned wh = (h < 2) ? w0 : w1;
            __half2 hp = *reinterpret_cast<__half2*>(&wh);
            float a = (h & 1) ? __high2float(hp) : __low2float(hp);
            uint2 u = __ldg(reinterpret_cast<const uint2*>(g_fth + (size_t)sve * HF + lane * 4));
            float2 f01 = __half22float2(*reinterpret_cast<__half2*>(&u.x));
            float2 f23 = __half22float2(*reinterpret_cast<__half2*>(&u.y));
            acc.x += a * f01.x; acc.y += a * f01.y;
            acc.z += a * f23.x; acc.w += a * f23.y;
            sacc += a;
        }
    }

    float inv = 1.0f / sacc;
    float4* op = reinterpret_cast<float4*>(out + (size_t)v * HF + lane * 4);
    float4 o = *op;
    o.x += acc.x * inv; o.y += acc.y * inv; o.z += acc.z * inv; o.w += acc.w * inv;
    *op = o;
}

// ---------------- launch: three-stream forked capture, 5 kernels ---------
static cudaStream_t g_s2 = nullptr, g_s3 = nullptr;
static cudaEvent_t g_evFork = nullptr, g_evJoin = nullptr, g_evFold = nullptr, g_evEE = nullptr;

extern "C" void kernel_launch(void* const* d_in, const int* in_sizes, int n_in,
                              void* d_out, int out_size)
{
    const float* nf   = (const float*)d_in[0];
    const float* ef   = (const float*)d_in[1];
    const int*   src  = (const int*)d_in[2];
    const int*   dst  = (const int*)d_in[3];
    const float* Wn   = (const float*)d_in[4];
    const float* We   = (const float*)d_in[5];
    const float* al   = (const float*)d_in[6];
    const float* ar   = (const float*)d_in[7];
    const float* ae   = (const float*)d_in[8];
    const float* Wr   = (const float*)d_in[9];
    const float* bias = (const float*)d_in[10];
    float* out = (float*)d_out;

    int V = in_sizes[0] / NODE_IN;
    int E = in_sizes[2];
    if (V > MAXV) V = MAXV;
    if (E > MAXE) E = MAXE;

    if (!g_s2) {
        cudaStreamCreateWithFlags(&g_s2, cudaStreamNonBlocking);
        cudaStreamCreateWithFlags(&g_s3, cudaStreamNonBlocking);
        cudaEventCreateWithFlags(&g_evFork, cudaEventDisableTiming);
        cudaEventCreateWithFlags(&g_evJoin, cudaEventDisableTiming);
        cudaEventCreateWithFlags(&g_evFold, cudaEventDisableTiming);
        cudaEventCreateWithFlags(&g_evEE, cudaEventDisableTiming);
    }

    const int smemProj = PROJ_ROWS * XS_LD * sizeof(float);   // ~33.8 KB
    int nch = (V + 1023) / 1024;                              // 49 blocks (<=148 SMs)

    cudaEventRecord(g_evFork, 0);
    cudaStreamWaitEvent(g_s2, g_evFork, 0);
    cudaStreamWaitEvent(g_s3, g_evFork, 0);

    k_fold<<<(NODE_IN * HF / 2 + 255) / 256, 256>>>(We, ae, Wn, Wr);  // #1 main
    cudaEventRecord(g_evFold, 0);

    // s3: ef-streaming edge GEMM, overlapped under nodeproj
    cudaStreamWaitEvent(g_s3, g_evFold, 0);
    k_ee<<<(E + 255) / 256, 256, 0, g_s3>>>(ef, E);                   // #2 s3
    cudaEventRecord(g_evEE, g_s3);

    // s2: fused CSR build (single persistent kernel, in-kernel grid barriers)
    k_csr<<<nch, 1024, 0, g_s2>>>(dst, E, V);                         // #3 s2
    cudaEventRecord(g_evJoin, g_s2);

    // main chain
    k_nodeproj<<<(V + PROJ_ROWS - 1) / PROJ_ROWS, 256, smemProj>>>(nf, bias, al, ar, out, V);  // #4 main (profiled)
    cudaStreamWaitEvent(0, g_evEE, 0);
    cudaStreamWaitEvent(0, g_evJoin, 0);
    k_agg<<<(V * 32 + 255) / 256, 256>>>(src, out, V);                // #5 main
}